// round 7
// baseline (speedup 1.0000x reference)
#include <cuda_runtime.h>
#include <cstdint>

#define N_NODES 100000
#define N_EDGES 600000
#define CH 128
#define NPB 64            // nodes per block tile (tail block handles 32)
#define NBLK 1563         // ceil(100000/64)
#define NCHUNK 98         // ceil(100000/1024)
#define AS_STRIDE 260     // 256 + 4 -> bank-conflict-free fragment LDS
#define AS_BYTES (NPB * AS_STRIDE * 4)

// ---------------- scratch (static device globals; no allocation) ----------------
__device__ int   g_deg[N_NODES];
__device__ float g_deginv[N_NODES];
__device__ int   g_off[N_NODES + 1];
__device__ int   g_cur[N_NODES];
__device__ int   g_col[N_EDGES];
__device__ int   g_chunksum[NCHUNK];
__device__ int   g_chunkoff[NCHUNK];
__device__ float g_h1[(size_t)N_NODES * CH];
__device__ float g_h2[(size_t)N_NODES * CH];
// fragment-ordered weights: pair index = (((wn*32 + kt)*4 + nt)*32 + lane), 2 floats each
__device__ float g_Wt2[128 * 256];
__device__ float g_Wt3[128 * 256];

// ---------------- helpers ----------------
__device__ __forceinline__ float tf32r(float x) {
    unsigned r;
    asm("cvt.rna.tf32.f32 %0, %1;" : "=r"(r) : "f"(x));   // tf32 cvt writes .b32
    return __uint_as_float(r);
}
__device__ __forceinline__ int warp_incl_scan(int v, int lane) {
    #pragma unroll
    for (int o = 1; o < 32; o <<= 1) {
        int t = __shfl_up_sync(0xffffffffu, v, o);
        if (lane >= o) v += t;
    }
    return v;
}
__device__ __forceinline__ void mma_tf32(float* c, const unsigned* a, const unsigned* b) {
    asm volatile(
        "mma.sync.aligned.m16n8k8.row.col.f32.tf32.tf32.f32 "
        "{%0,%1,%2,%3}, {%4,%5,%6,%7}, {%8,%9}, {%0,%1,%2,%3};"
        : "+f"(c[0]), "+f"(c[1]), "+f"(c[2]), "+f"(c[3])
        : "r"(a[0]), "r"(a[1]), "r"(a[2]), "r"(a[3]), "r"(b[0]), "r"(b[1]));
}

// ---------------- weight prep: fragment-order shuffle + concat + tf32 round ----------------
// pair p: lane=p&31, nt=(p>>5)&3, kt=(p>>7)&31, wn=(p>>12)&3
//   gid=lane>>2, tig=lane&3, n = wn*32 + nt*8 + gid, k = kt*8 + tig
//   value0 = W[n][k], value1 = W[n][k+4]   (k<128 -> Wl[k][n], else Wr[k-128][n])
__global__ void prep_kernel(const float* __restrict__ W2l, const float* __restrict__ W2r,
                            const float* __restrict__ W3l, const float* __restrict__ W3r) {
    int p = blockIdx.x * blockDim.x + threadIdx.x;   // 16384 pairs
    if (p >= 16384) return;
    int lane = p & 31;
    int nt   = (p >> 5) & 3;
    int kt   = (p >> 7) & 31;
    int wn   = (p >> 12) & 3;
    int gid = lane >> 2, tig = lane & 3;
    int n  = wn * 32 + nt * 8 + gid;
    int k0 = kt * 8 + tig;
    int k1 = k0 + 4;

    float v2a = (k0 < 128) ? W2l[k0 * CH + n] : W2r[(k0 - 128) * CH + n];
    float v2b = (k1 < 128) ? W2l[k1 * CH + n] : W2r[(k1 - 128) * CH + n];
    float v3a = (k0 < 128) ? W3l[k0 * CH + n] : W3r[(k0 - 128) * CH + n];
    float v3b = (k1 < 128) ? W3l[k1 * CH + n] : W3r[(k1 - 128) * CH + n];
    g_Wt2[p * 2 + 0] = tf32r(v2a);
    g_Wt2[p * 2 + 1] = tf32r(v2b);
    g_Wt3[p * 2 + 0] = tf32r(v3a);
    g_Wt3[p * 2 + 1] = tf32r(v3b);
}

// ---------------- CSR build ----------------
__global__ void zero_deg_kernel() {
    int i = blockIdx.x * blockDim.x + threadIdx.x;
    if (i < N_NODES) g_deg[i] = 0;
}

__global__ void hist_kernel(const int* __restrict__ dst) {
    int i = blockIdx.x * blockDim.x + threadIdx.x;
    if (i < N_EDGES) atomicAdd(&g_deg[dst[i]], 1);
}

// phase 1: per-1024-chunk inclusive scan (parallel over chunks)
__global__ void scan1_kernel() {
    __shared__ int wsum[32];
    int b = blockIdx.x, tid = threadIdx.x;
    int wid = tid >> 5, lane = tid & 31;
    int i = b * 1024 + tid;
    int v = (i < N_NODES) ? g_deg[i] : 0;
    if (i < N_NODES) g_deginv[i] = (v > 0) ? (1.0f / (float)v) : 0.0f;

    int incl = warp_incl_scan(v, lane);
    if (lane == 31) wsum[wid] = incl;
    __syncthreads();
    if (wid == 0) {
        int ws = wsum[lane];
        int wi = warp_incl_scan(ws, lane);
        wsum[lane] = wi - ws;   // exclusive warp prefix
    }
    __syncthreads();
    int inclusive = wsum[wid] + incl;
    if (i < N_NODES) g_off[i + 1] = inclusive;      // chunk-local inclusive
    if (tid == 1023) g_chunksum[b] = inclusive;     // chunk total
}

// phase 2: scan the 98 chunk sums
__global__ void scan2_kernel() {
    __shared__ int ws[4];
    int tid = threadIdx.x, wid = tid >> 5, lane = tid & 31;
    int v = (tid < NCHUNK) ? g_chunksum[tid] : 0;
    int incl = warp_incl_scan(v, lane);
    if (lane == 31) ws[wid] = incl;
    __syncthreads();
    int woff = 0;
    #pragma unroll
    for (int w = 0; w < 4; w++) if (w < wid) woff += ws[w];
    if (tid < NCHUNK) g_chunkoff[tid] = woff + incl - v;   // exclusive chunk offset
}

// phase 3: add chunk offsets back, produce g_off / g_cur
__global__ void scan3_kernel() {
    int b = blockIdx.x, tid = threadIdx.x;
    int i = b * 1024 + tid;
    if (i < N_NODES) {
        int incl = g_off[i + 1] + g_chunkoff[b];
        g_off[i + 1] = incl;
        g_cur[i]     = incl - g_deg[i];
        if (i == 0) g_off[0] = 0;
    }
}

__global__ void fill_kernel(const int* __restrict__ src, const int* __restrict__ dst) {
    int i = blockIdx.x * blockDim.x + threadIdx.x;
    if (i < N_EDGES) {
        int d   = dst[i];
        int pos = atomicAdd(&g_cur[d], 1);
        g_col[pos] = src[i];
    }
}

// ---------------- layer 1 (K = 3, exact fp32) ----------------
__global__ void layer1_kernel(const float* __restrict__ x,
                              const float* __restrict__ Wl,
                              const float* __restrict__ Wr,
                              const float* __restrict__ b,
                              float* __restrict__ hout) {
    __shared__ float aggx[64][4];
    __shared__ float xs[64][4];
    int tid  = threadIdx.x;
    int warp = tid >> 5, lane = tid & 31;
    int base = blockIdx.x * 64;

    for (int n = warp; n < 64; n += 4) {
        int node = base + n;
        if (node >= N_NODES) break;
        int s0 = g_off[node], e0 = g_off[node + 1];
        float a0 = 0.f, a1 = 0.f, a2 = 0.f;
        for (int idx = s0 + lane; idx < e0; idx += 32) {
            int j = g_col[idx];
            a0 += x[j * 3 + 0];
            a1 += x[j * 3 + 1];
            a2 += x[j * 3 + 2];
        }
        #pragma unroll
        for (int o = 16; o > 0; o >>= 1) {
            a0 += __shfl_xor_sync(0xffffffffu, a0, o);
            a1 += __shfl_xor_sync(0xffffffffu, a1, o);
            a2 += __shfl_xor_sync(0xffffffffu, a2, o);
        }
        if (lane == 0) {
            float di = g_deginv[node];
            aggx[n][0] = a0 * di; aggx[n][1] = a1 * di; aggx[n][2] = a2 * di;
            xs[n][0] = x[node * 3 + 0];
            xs[n][1] = x[node * 3 + 1];
            xs[n][2] = x[node * 3 + 2];
        }
    }
    __syncthreads();

    int t = tid;
    float wl0 = Wl[0 * CH + t], wl1 = Wl[1 * CH + t], wl2 = Wl[2 * CH + t];
    float wr0 = Wr[0 * CH + t], wr1 = Wr[1 * CH + t], wr2 = Wr[2 * CH + t];
    float bb  = b[t];
    for (int n = 0; n < 64; n++) {
        int node = base + n;
        if (node >= N_NODES) break;
        float acc = bb;
        acc += aggx[n][0] * wl0 + aggx[n][1] * wl1 + aggx[n][2] * wl2;
        acc += xs[n][0]   * wr0 + xs[n][1]   * wr1 + xs[n][2]   * wr2;
        hout[(size_t)node * CH + t] = fmaxf(acc, 0.0f);
    }
}

// ---------------- layers 2/3: gather-aggregate + tf32 tensor-core GEMM + relu ----------------
// A tile = [agg | own] : 64 nodes x 256 K. 8 warps = 2(M) x 4(N); each warp does a
// 32x32 output tile (mt=2 m16-tiles, nt=4 n8-tiles) -> balanced A-smem/B-L1 traffic.
__global__ void __launch_bounds__(256)
layerTC_kernel(const float* __restrict__ hin, float* __restrict__ hout,
               const float* __restrict__ Wt, const float* __restrict__ bias) {
    extern __shared__ __align__(16) float As[];   // [NPB][AS_STRIDE] = 66,560 B

    int tid  = threadIdx.x;
    int warp = tid >> 5, lane = tid & 31;
    int base = blockIdx.x * NPB;

    // ---- Phase A: mean-aggregate + own row, tf32-rounded, into shared ----
    for (int n = warp; n < NPB; n += 8) {
        int node = base + n;
        if (node >= N_NODES) break;      // tail block: leave rows unused
        float4 own = *(const float4*)&hin[(size_t)node * CH + lane * 4];

        int s0 = g_off[node], e0 = g_off[node + 1];
        float4 A0 = make_float4(0.f, 0.f, 0.f, 0.f);
        float4 A1 = A0, A2 = A0, A3 = A0;
        int idx = s0;
        for (; idx + 4 <= e0; idx += 4) {
            int j0 = g_col[idx + 0], j1 = g_col[idx + 1];
            int j2 = g_col[idx + 2], j3 = g_col[idx + 3];
            float4 v0 = *(const float4*)&hin[(size_t)j0 * CH + lane * 4];
            float4 v1 = *(const float4*)&hin[(size_t)j1 * CH + lane * 4];
            float4 v2 = *(const float4*)&hin[(size_t)j2 * CH + lane * 4];
            float4 v3 = *(const float4*)&hin[(size_t)j3 * CH + lane * 4];
            A0.x += v0.x; A0.y += v0.y; A0.z += v0.z; A0.w += v0.w;
            A1.x += v1.x; A1.y += v1.y; A1.z += v1.z; A1.w += v1.w;
            A2.x += v2.x; A2.y += v2.y; A2.z += v2.z; A2.w += v2.w;
            A3.x += v3.x; A3.y += v3.y; A3.z += v3.z; A3.w += v3.w;
        }
        for (; idx < e0; idx++) {
            int j = g_col[idx];
            float4 v = *(const float4*)&hin[(size_t)j * CH + lane * 4];
            A0.x += v.x; A0.y += v.y; A0.z += v.z; A0.w += v.w;
        }
        float di = g_deginv[node];
        float4 agg;
        agg.x = tf32r(((A0.x + A1.x) + (A2.x + A3.x)) * di);
        agg.y = tf32r(((A0.y + A1.y) + (A2.y + A3.y)) * di);
        agg.z = tf32r(((A0.z + A1.z) + (A2.z + A3.z)) * di);
        agg.w = tf32r(((A0.w + A1.w) + (A2.w + A3.w)) * di);
        *(float4*)&As[n * AS_STRIDE + lane * 4] = agg;
        float4 ownr;
        ownr.x = tf32r(own.x); ownr.y = tf32r(own.y);
        ownr.z = tf32r(own.z); ownr.w = tf32r(own.w);
        *(float4*)&As[n * AS_STRIDE + 128 + lane * 4] = ownr;
    }
    __syncthreads();

    // ---- Phase B: 64x128 = (64x256) @ (256x128), warp tile 32x32 ----
    int wm = warp >> 2;          // 0..1  -> M rows [wm*32, wm*32+32)
    int wn = warp & 3;           // 0..3  -> N cols [wn*32, wn*32+32)
    int gid = lane >> 2, tig = lane & 3;

    float acc[2][4][4];
    #pragma unroll
    for (int mt = 0; mt < 2; mt++)
        #pragma unroll
        for (int nt = 0; nt < 4; nt++)
            #pragma unroll
            for (int r = 0; r < 4; r++) acc[mt][nt][r] = 0.0f;

    const float2* Wf = (const float2*)Wt;
    const unsigned* AsU = (const unsigned*)As;

    #pragma unroll 4
    for (int kt = 0; kt < 32; kt++) {
        // 4 consecutive coalesced LDG.64: B frags for nt = 0..3
        unsigned i0 = ((unsigned)(wn * 32 + kt) * 4) * 32 + lane;
        float2 f0 = Wf[i0];
        float2 f1 = Wf[i0 + 32];
        float2 f2 = Wf[i0 + 64];
        float2 f3 = Wf[i0 + 96];
        unsigned bfr[4][2] = {
            { __float_as_uint(f0.x), __float_as_uint(f0.y) },
            { __float_as_uint(f1.x), __float_as_uint(f1.y) },
            { __float_as_uint(f2.x), __float_as_uint(f2.y) },
            { __float_as_uint(f3.x), __float_as_uint(f3.y) } };

        unsigned kc = kt * 8;
        #pragma unroll
        for (int mt = 0; mt < 2; mt++) {
            unsigned r0 = (unsigned)(wm * 32 + mt * 16 + gid) * AS_STRIDE + kc + tig;
            unsigned a[4];
            a[0] = AsU[r0];
            a[1] = AsU[r0 + 8 * AS_STRIDE];
            a[2] = AsU[r0 + 4];
            a[3] = AsU[r0 + 8 * AS_STRIDE + 4];
            #pragma unroll
            for (int nt = 0; nt < 4; nt++)
                mma_tf32(acc[mt][nt], a, bfr[nt]);
        }
    }

    // ---- epilogue: bias + relu + store (float2, cols adjacent) ----
    #pragma unroll
    for (int nt = 0; nt < 4; nt++) {
        int col = wn * 32 + nt * 8 + tig * 2;
        float bb0 = bias[col], bb1 = bias[col + 1];
        #pragma unroll
        for (int mt = 0; mt < 2; mt++) {
            int row = base + wm * 32 + mt * 16 + gid;
            if (row < N_NODES) {
                float2 v;
                v.x = fmaxf(acc[mt][nt][0] + bb0, 0.0f);
                v.y = fmaxf(acc[mt][nt][1] + bb1, 0.0f);
                *(float2*)&hout[(size_t)row * CH + col] = v;
            }
            if (row + 8 < N_NODES) {
                float2 v;
                v.x = fmaxf(acc[mt][nt][2] + bb0, 0.0f);
                v.y = fmaxf(acc[mt][nt][3] + bb1, 0.0f);
                *(float2*)&hout[(size_t)(row + 8) * CH + col] = v;
            }
        }
    }
}

// ---------------- launch ----------------
extern "C" void kernel_launch(void* const* d_in, const int* in_sizes, int n_in,
                              void* d_out, int out_size) {
    const float* x   = (const float*)d_in[0];
    const int*   ei  = (const int*)d_in[1];      // [2, E]
    const float* W1l = (const float*)d_in[2];
    const float* W1r = (const float*)d_in[3];
    const float* b1  = (const float*)d_in[4];
    const float* W2l = (const float*)d_in[5];
    const float* W2r = (const float*)d_in[6];
    const float* b2  = (const float*)d_in[7];
    const float* W3l = (const float*)d_in[8];
    const float* W3r = (const float*)d_in[9];
    const float* b3  = (const float*)d_in[10];
    float* out = (float*)d_out;

    const int* src = ei;
    const int* dst = ei + N_EDGES;

    float* h1; float* h2; float* Wt2; float* Wt3;
    cudaGetSymbolAddress((void**)&h1, g_h1);
    cudaGetSymbolAddress((void**)&h2, g_h2);
    cudaGetSymbolAddress((void**)&Wt2, g_Wt2);
    cudaGetSymbolAddress((void**)&Wt3, g_Wt3);

    // dynamic smem opt-in (idempotent host-side call; not a stream op)
    cudaFuncSetAttribute(layerTC_kernel,
                         cudaFuncAttributeMaxDynamicSharedMemorySize, AS_BYTES);

    // weight prep + CSR build
    prep_kernel<<<(16384 + 255) / 256, 256>>>(W2l, W2r, W3l, W3r);
    zero_deg_kernel<<<(N_NODES + 255) / 256, 256>>>();
    hist_kernel<<<(N_EDGES + 255) / 256, 256>>>(dst);
    scan1_kernel<<<NCHUNK, 1024>>>();
    scan2_kernel<<<1, 128>>>();
    scan3_kernel<<<NCHUNK, 1024>>>();
    fill_kernel<<<(N_EDGES + 255) / 256, 256>>>(src, dst);

    // layers
    layer1_kernel<<<(N_NODES + 63) / 64, 128>>>(x, W1l, W1r, b1, h1);
    layerTC_kernel<<<NBLK, 256, AS_BYTES>>>(h1, h2, Wt2, b2);
    layerTC_kernel<<<NBLK, 256, AS_BYTES>>>(h2, out, Wt3, b3);
}

// round 8
// speedup vs baseline: 1.1742x; 1.1742x over previous
#include <cuda_runtime.h>
#include <cstdint>

#define N_NODES 100000
#define N_EDGES 600000
#define CH 128
#define NPB 64            // nodes per block tile (tail block handles 32)
#define NBLK 1563         // ceil(100000/64)
#define NCHUNK 98         // ceil(100000/1024)
#define AS_STRIDE 132     // 128 + 4 -> bank-conflict-free fragment LDS

// ---------------- scratch (static device globals; no allocation) ----------------
__device__ int   g_deg[N_NODES];
__device__ float g_deginv[N_NODES];
__device__ int   g_off[N_NODES + 1];
__device__ int   g_cur[N_NODES];
__device__ int   g_col[N_EDGES];
__device__ int   g_chunksum[NCHUNK];
__device__ int   g_chunkoff[NCHUNK];
__device__ float g_h1[(size_t)N_NODES * CH];
__device__ float g_h2[(size_t)N_NODES * CH];
// fragment-ordered weights: pair idx = ((((wn*2+pass)*16 + kt)*4 + nt)*32 + lane), 2 floats each
__device__ float g_Wt2[128 * 256];
__device__ float g_Wt3[128 * 256];

// ---------------- helpers ----------------
__device__ __forceinline__ float tf32r(float x) {
    unsigned r;
    asm("cvt.rna.tf32.f32 %0, %1;" : "=r"(r) : "f"(x));   // tf32 cvt writes .b32
    return __uint_as_float(r);
}
__device__ __forceinline__ int warp_incl_scan(int v, int lane) {
    #pragma unroll
    for (int o = 1; o < 32; o <<= 1) {
        int t = __shfl_up_sync(0xffffffffu, v, o);
        if (lane >= o) v += t;
    }
    return v;
}
__device__ __forceinline__ void mma_tf32(float* c, const unsigned* a, const unsigned* b) {
    asm volatile(
        "mma.sync.aligned.m16n8k8.row.col.f32.tf32.tf32.f32 "
        "{%0,%1,%2,%3}, {%4,%5,%6,%7}, {%8,%9}, {%0,%1,%2,%3};"
        : "+f"(c[0]), "+f"(c[1]), "+f"(c[2]), "+f"(c[3])
        : "r"(a[0]), "r"(a[1]), "r"(a[2]), "r"(a[3]), "r"(b[0]), "r"(b[1]));
}

// ---------------- weight prep: fragment-order shuffle + split-K + tf32 round ----------------
// pair p: lane=p&31, nt=(p>>5)&3, kt=(p>>7)&15, pass=(p>>11)&1, wn=(p>>12)&3
//   gid=lane>>2, tig=lane&3, n = wn*32 + nt*8 + gid, k = kt*8 + tig
//   pass 0 -> Wl[k][n], pass 1 -> Wr[k][n]; value1 at k+4.
__global__ void prep_kernel(const float* __restrict__ W2l, const float* __restrict__ W2r,
                            const float* __restrict__ W3l, const float* __restrict__ W3r) {
    int p = blockIdx.x * blockDim.x + threadIdx.x;   // 16384 pairs
    if (p >= 16384) return;
    int lane = p & 31;
    int nt   = (p >> 5) & 3;
    int kt   = (p >> 7) & 15;
    int pass = (p >> 11) & 1;
    int wn   = (p >> 12) & 3;
    int gid = lane >> 2, tig = lane & 3;
    int n  = wn * 32 + nt * 8 + gid;
    int k0 = kt * 8 + tig;
    int k1 = k0 + 4;

    const float* Wa2 = pass ? W2r : W2l;
    const float* Wa3 = pass ? W3r : W3l;
    g_Wt2[p * 2 + 0] = tf32r(Wa2[k0 * CH + n]);
    g_Wt2[p * 2 + 1] = tf32r(Wa2[k1 * CH + n]);
    g_Wt3[p * 2 + 0] = tf32r(Wa3[k0 * CH + n]);
    g_Wt3[p * 2 + 1] = tf32r(Wa3[k1 * CH + n]);
}

// ---------------- CSR build ----------------
__global__ void zero_deg_kernel() {
    int i = blockIdx.x * blockDim.x + threadIdx.x;
    if (i < N_NODES) g_deg[i] = 0;
}

__global__ void hist_kernel(const int* __restrict__ dst) {
    int i = blockIdx.x * blockDim.x + threadIdx.x;
    if (i < N_EDGES) atomicAdd(&g_deg[dst[i]], 1);
}

// phase 1: per-1024-chunk inclusive scan (parallel over chunks)
__global__ void scan1_kernel() {
    __shared__ int wsum[32];
    int b = blockIdx.x, tid = threadIdx.x;
    int wid = tid >> 5, lane = tid & 31;
    int i = b * 1024 + tid;
    int v = (i < N_NODES) ? g_deg[i] : 0;
    if (i < N_NODES) g_deginv[i] = (v > 0) ? (1.0f / (float)v) : 0.0f;

    int incl = warp_incl_scan(v, lane);
    if (lane == 31) wsum[wid] = incl;
    __syncthreads();
    if (wid == 0) {
        int ws = wsum[lane];
        int wi = warp_incl_scan(ws, lane);
        wsum[lane] = wi - ws;   // exclusive warp prefix
    }
    __syncthreads();
    int inclusive = wsum[wid] + incl;
    if (i < N_NODES) g_off[i + 1] = inclusive;      // chunk-local inclusive
    if (tid == 1023) g_chunksum[b] = inclusive;     // chunk total
}

// phase 2: scan the 98 chunk sums
__global__ void scan2_kernel() {
    __shared__ int ws[4];
    int tid = threadIdx.x, wid = tid >> 5, lane = tid & 31;
    int v = (tid < NCHUNK) ? g_chunksum[tid] : 0;
    int incl = warp_incl_scan(v, lane);
    if (lane == 31) ws[wid] = incl;
    __syncthreads();
    int woff = 0;
    #pragma unroll
    for (int w = 0; w < 4; w++) if (w < wid) woff += ws[w];
    if (tid < NCHUNK) g_chunkoff[tid] = woff + incl - v;   // exclusive chunk offset
}

// phase 3: add chunk offsets back, produce g_off / g_cur
__global__ void scan3_kernel() {
    int b = blockIdx.x, tid = threadIdx.x;
    int i = b * 1024 + tid;
    if (i < N_NODES) {
        int incl = g_off[i + 1] + g_chunkoff[b];
        g_off[i + 1] = incl;
        g_cur[i]     = incl - g_deg[i];
        if (i == 0) g_off[0] = 0;
    }
}

__global__ void fill_kernel(const int* __restrict__ src, const int* __restrict__ dst) {
    int i = blockIdx.x * blockDim.x + threadIdx.x;
    if (i < N_EDGES) {
        int d   = dst[i];
        int pos = atomicAdd(&g_cur[d], 1);
        g_col[pos] = src[i];
    }
}

// ---------------- layer 1 (K = 3, exact fp32) ----------------
__global__ void layer1_kernel(const float* __restrict__ x,
                              const float* __restrict__ Wl,
                              const float* __restrict__ Wr,
                              const float* __restrict__ b,
                              float* __restrict__ hout) {
    __shared__ float aggx[64][4];
    __shared__ float xs[64][4];
    int tid  = threadIdx.x;
    int warp = tid >> 5, lane = tid & 31;
    int base = blockIdx.x * 64;

    for (int n = warp; n < 64; n += 4) {
        int node = base + n;
        if (node >= N_NODES) break;
        int s0 = g_off[node], e0 = g_off[node + 1];
        float a0 = 0.f, a1 = 0.f, a2 = 0.f;
        for (int idx = s0 + lane; idx < e0; idx += 32) {
            int j = g_col[idx];
            a0 += x[j * 3 + 0];
            a1 += x[j * 3 + 1];
            a2 += x[j * 3 + 2];
        }
        #pragma unroll
        for (int o = 16; o > 0; o >>= 1) {
            a0 += __shfl_xor_sync(0xffffffffu, a0, o);
            a1 += __shfl_xor_sync(0xffffffffu, a1, o);
            a2 += __shfl_xor_sync(0xffffffffu, a2, o);
        }
        if (lane == 0) {
            float di = g_deginv[node];
            aggx[n][0] = a0 * di; aggx[n][1] = a1 * di; aggx[n][2] = a2 * di;
            xs[n][0] = x[node * 3 + 0];
            xs[n][1] = x[node * 3 + 1];
            xs[n][2] = x[node * 3 + 2];
        }
    }
    __syncthreads();

    int t = tid;
    float wl0 = Wl[0 * CH + t], wl1 = Wl[1 * CH + t], wl2 = Wl[2 * CH + t];
    float wr0 = Wr[0 * CH + t], wr1 = Wr[1 * CH + t], wr2 = Wr[2 * CH + t];
    float bb  = b[t];
    for (int n = 0; n < 64; n++) {
        int node = base + n;
        if (node >= N_NODES) break;
        float acc = bb;
        acc += aggx[n][0] * wl0 + aggx[n][1] * wl1 + aggx[n][2] * wl2;
        acc += xs[n][0]   * wr0 + xs[n][1]   * wr1 + xs[n][2]   * wr2;
        hout[(size_t)node * CH + t] = fmaxf(acc, 0.0f);
    }
}

// ---------------- layers 2/3: split-K two-pass tensor-core GEMM ----------------
// Pass 0: As = agg (K 0..127) vs Wl; pass 1: As = own vs Wr; same accumulators.
// 8 warps = 2(M) x 4(N); warp tile 32 rows x 32 cols. smem = 64 x 132 x 4 = 33.8 KB.
__global__ void __launch_bounds__(256, 4)
layerTC_kernel(const float* __restrict__ hin, float* __restrict__ hout,
               const float* __restrict__ Wt, const float* __restrict__ bias) {
    __shared__ __align__(16) float As[NPB][AS_STRIDE];

    int tid  = threadIdx.x;
    int warp = tid >> 5, lane = tid & 31;
    int base = blockIdx.x * NPB;

    int wm = warp >> 2;          // 0..1  -> M rows [wm*32, wm*32+32)
    int wn = warp & 3;           // 0..3  -> N cols [wn*32, wn*32+32)
    int gid = lane >> 2, tig = lane & 3;

    float acc[2][4][4];
    #pragma unroll
    for (int mt = 0; mt < 2; mt++)
        #pragma unroll
        for (int nt = 0; nt < 4; nt++)
            #pragma unroll
            for (int r = 0; r < 4; r++) acc[mt][nt][r] = 0.0f;

    const float2* Wf = (const float2*)Wt;
    const unsigned* AsU = (const unsigned*)&As[0][0];

    #pragma unroll
    for (int pass = 0; pass < 2; pass++) {
        // ---- Phase A: fill As with agg (pass 0) or own rows (pass 1) ----
        if (pass == 0) {
            for (int n = warp; n < NPB; n += 8) {
                int node = base + n;
                if (node >= N_NODES) break;      // tail block
                int s0 = g_off[node], e0 = g_off[node + 1];
                float4 A0 = make_float4(0.f, 0.f, 0.f, 0.f);
                float4 A1 = A0, A2 = A0, A3 = A0;
                int idx = s0;
                for (; idx + 4 <= e0; idx += 4) {
                    int j0 = g_col[idx + 0], j1 = g_col[idx + 1];
                    int j2 = g_col[idx + 2], j3 = g_col[idx + 3];
                    float4 v0 = *(const float4*)&hin[(size_t)j0 * CH + lane * 4];
                    float4 v1 = *(const float4*)&hin[(size_t)j1 * CH + lane * 4];
                    float4 v2 = *(const float4*)&hin[(size_t)j2 * CH + lane * 4];
                    float4 v3 = *(const float4*)&hin[(size_t)j3 * CH + lane * 4];
                    A0.x += v0.x; A0.y += v0.y; A0.z += v0.z; A0.w += v0.w;
                    A1.x += v1.x; A1.y += v1.y; A1.z += v1.z; A1.w += v1.w;
                    A2.x += v2.x; A2.y += v2.y; A2.z += v2.z; A2.w += v2.w;
                    A3.x += v3.x; A3.y += v3.y; A3.z += v3.z; A3.w += v3.w;
                }
                for (; idx < e0; idx++) {
                    int j = g_col[idx];
                    float4 v = *(const float4*)&hin[(size_t)j * CH + lane * 4];
                    A0.x += v.x; A0.y += v.y; A0.z += v.z; A0.w += v.w;
                }
                float di = g_deginv[node];
                float4 agg;
                agg.x = tf32r(((A0.x + A1.x) + (A2.x + A3.x)) * di);
                agg.y = tf32r(((A0.y + A1.y) + (A2.y + A3.y)) * di);
                agg.z = tf32r(((A0.z + A1.z) + (A2.z + A3.z)) * di);
                agg.w = tf32r(((A0.w + A1.w) + (A2.w + A3.w)) * di);
                *(float4*)&As[n][lane * 4] = agg;
            }
        } else {
            for (int n = warp; n < NPB; n += 8) {
                int node = base + n;
                if (node >= N_NODES) break;
                float4 own = *(const float4*)&hin[(size_t)node * CH + lane * 4];
                float4 o;
                o.x = tf32r(own.x); o.y = tf32r(own.y);
                o.z = tf32r(own.z); o.w = tf32r(own.w);
                *(float4*)&As[n][lane * 4] = o;
            }
        }
        __syncthreads();

        // ---- Phase B: accumulate (64x128) @ (128x128) ----
        #pragma unroll 4
        for (int kt = 0; kt < 16; kt++) {
            unsigned i0 = (((unsigned)(wn * 2 + pass) * 16 + kt) * 4) * 32 + lane;
            float2 f0 = Wf[i0];
            float2 f1 = Wf[i0 + 32];
            float2 f2 = Wf[i0 + 64];
            float2 f3 = Wf[i0 + 96];
            unsigned bfr[4][2] = {
                { __float_as_uint(f0.x), __float_as_uint(f0.y) },
                { __float_as_uint(f1.x), __float_as_uint(f1.y) },
                { __float_as_uint(f2.x), __float_as_uint(f2.y) },
                { __float_as_uint(f3.x), __float_as_uint(f3.y) } };

            unsigned kc = kt * 8;
            #pragma unroll
            for (int mt = 0; mt < 2; mt++) {
                unsigned r0 = (unsigned)(wm * 32 + mt * 16 + gid) * AS_STRIDE + kc + tig;
                unsigned a[4];
                a[0] = AsU[r0];
                a[1] = AsU[r0 + 8 * AS_STRIDE];
                a[2] = AsU[r0 + 4];
                a[3] = AsU[r0 + 8 * AS_STRIDE + 4];
                #pragma unroll
                for (int nt = 0; nt < 4; nt++)
                    mma_tf32(acc[mt][nt], a, bfr[nt]);
            }
        }
        __syncthreads();   // pass-1 Phase A may not overwrite before all reads done
    }

    // ---- epilogue: bias + relu + store (float2, cols adjacent) ----
    #pragma unroll
    for (int nt = 0; nt < 4; nt++) {
        int col = wn * 32 + nt * 8 + tig * 2;
        float bb0 = bias[col], bb1 = bias[col + 1];
        #pragma unroll
        for (int mt = 0; mt < 2; mt++) {
            int row = base + wm * 32 + mt * 16 + gid;
            if (row < N_NODES) {
                float2 v;
                v.x = fmaxf(acc[mt][nt][0] + bb0, 0.0f);
                v.y = fmaxf(acc[mt][nt][1] + bb1, 0.0f);
                *(float2*)&hout[(size_t)row * CH + col] = v;
            }
            if (row + 8 < N_NODES) {
                float2 v;
                v.x = fmaxf(acc[mt][nt][2] + bb0, 0.0f);
                v.y = fmaxf(acc[mt][nt][3] + bb1, 0.0f);
                *(float2*)&hout[(size_t)(row + 8) * CH + col] = v;
            }
        }
    }
}

// ---------------- launch ----------------
extern "C" void kernel_launch(void* const* d_in, const int* in_sizes, int n_in,
                              void* d_out, int out_size) {
    const float* x   = (const float*)d_in[0];
    const int*   ei  = (const int*)d_in[1];      // [2, E]
    const float* W1l = (const float*)d_in[2];
    const float* W1r = (const float*)d_in[3];
    const float* b1  = (const float*)d_in[4];
    const float* W2l = (const float*)d_in[5];
    const float* W2r = (const float*)d_in[6];
    const float* b2  = (const float*)d_in[7];
    const float* W3l = (const float*)d_in[8];
    const float* W3r = (const float*)d_in[9];
    const float* b3  = (const float*)d_in[10];
    float* out = (float*)d_out;

    const int* src = ei;
    const int* dst = ei + N_EDGES;

    float* h1; float* h2; float* Wt2; float* Wt3;
    cudaGetSymbolAddress((void**)&h1, g_h1);
    cudaGetSymbolAddress((void**)&h2, g_h2);
    cudaGetSymbolAddress((void**)&Wt2, g_Wt2);
    cudaGetSymbolAddress((void**)&Wt3, g_Wt3);

    // weight prep + CSR build
    prep_kernel<<<(16384 + 255) / 256, 256>>>(W2l, W2r, W3l, W3r);
    zero_deg_kernel<<<(N_NODES + 255) / 256, 256>>>();
    hist_kernel<<<(N_EDGES + 255) / 256, 256>>>(dst);
    scan1_kernel<<<NCHUNK, 1024>>>();
    scan2_kernel<<<1, 128>>>();
    scan3_kernel<<<NCHUNK, 1024>>>();
    fill_kernel<<<(N_EDGES + 255) / 256, 256>>>(src, dst);

    // layers
    layer1_kernel<<<(N_NODES + 63) / 64, 128>>>(x, W1l, W1r, b1, h1);
    layerTC_kernel<<<NBLK, 256>>>(h1, h2, Wt2, b2);
    layerTC_kernel<<<NBLK, 256>>>(h2, out, Wt3, b3);
}

// round 10
// speedup vs baseline: 1.3736x; 1.1698x over previous
#include <cuda_runtime.h>
#include <cuda_fp16.h>
#include <cstdint>

#define N_NODES 100000
#define N_EDGES 600000
#define CH 128
#define NPB 64            // nodes per block tile (tail block handles 32)
#define NBLK 1563         // ceil(100000/64)
#define NCHUNK 98         // ceil(100000/1024)
#define AS_H2 68          // half2 per row: 64 + 4 pad -> conflict-free fragment LDS

// ---------------- scratch (static device globals; no allocation) ----------------
__device__ int    g_deg[N_NODES];
__device__ float  g_deginv[N_NODES];
__device__ int    g_off[N_NODES + 1];
__device__ int    g_cur[N_NODES];
__device__ int    g_col[N_EDGES];
__device__ int    g_chunksum[NCHUNK];
__device__ int    g_chunkoff[NCHUNK];
__device__ float  g_h1[(size_t)N_NODES * CH];
__device__ float  g_h2[(size_t)N_NODES * CH];
// fp16 fragment-ordered weights: uint4 idx = ((((wn*2+pass)*8 + kt)*2 + g)*32 + lane)
//   holding {b0,b1} for nt=g*2 and nt=g*2+1
__device__ __align__(16) __half g_Wt2[128 * 256];
__device__ __align__(16) __half g_Wt3[128 * 256];

// ---------------- helpers ----------------
__device__ __forceinline__ int warp_incl_scan(int v, int lane) {
    #pragma unroll
    for (int o = 1; o < 32; o <<= 1) {
        int t = __shfl_up_sync(0xffffffffu, v, o);
        if (lane >= o) v += t;
    }
    return v;
}
__device__ __forceinline__ void mma_f16(float* c, const unsigned* a, const unsigned* b) {
    asm volatile(
        "mma.sync.aligned.m16n8k16.row.col.f32.f16.f16.f32 "
        "{%0,%1,%2,%3}, {%4,%5,%6,%7}, {%8,%9}, {%0,%1,%2,%3};"
        : "+f"(c[0]), "+f"(c[1]), "+f"(c[2]), "+f"(c[3])
        : "r"(a[0]), "r"(a[1]), "r"(a[2]), "r"(a[3]), "r"(b[0]), "r"(b[1]));
}
__device__ __forceinline__ unsigned h2u(__half2 h) {
    return *reinterpret_cast<unsigned*>(&h);
}

// ---------------- weight prep: fp16 fragment-order shuffle + split-K ----------------
// uint4 p: lane=p&31, g=(p>>5)&1, kt=(p>>6)&7, pass=(p>>9)&1, wn=(p>>10)&3
//   gid=lane>>2, tig=lane&3, k0 = kt*16 + tig*2 (within the pass's K=128)
//   for j in {0,1}: nt=g*2+j, n=wn*32+nt*8+gid
//     reg0 = {W[k0][n], W[k0+1][n]}, reg1 = {W[k0+8][n], W[k0+9][n]}
__global__ void prep_kernel(const float* __restrict__ W2l, const float* __restrict__ W2r,
                            const float* __restrict__ W3l, const float* __restrict__ W3r) {
    int p = blockIdx.x * blockDim.x + threadIdx.x;   // 4096 uint4
    if (p >= 4096) return;
    int lane = p & 31;
    int g    = (p >> 5) & 1;
    int kt   = (p >> 6) & 7;
    int pass = (p >> 9) & 1;
    int wn   = (p >> 10) & 3;
    int gid = lane >> 2, tig = lane & 3;
    int k0 = kt * 16 + tig * 2;

    const float* Wa2 = pass ? W2r : W2l;
    const float* Wa3 = pass ? W3r : W3l;

    unsigned out2[4], out3[4];
    #pragma unroll
    for (int j = 0; j < 2; j++) {
        int n = wn * 32 + (g * 2 + j) * 8 + gid;
        out2[j * 2 + 0] = h2u(__floats2half2_rn(Wa2[(k0 + 0) * CH + n], Wa2[(k0 + 1) * CH + n]));
        out2[j * 2 + 1] = h2u(__floats2half2_rn(Wa2[(k0 + 8) * CH + n], Wa2[(k0 + 9) * CH + n]));
        out3[j * 2 + 0] = h2u(__floats2half2_rn(Wa3[(k0 + 0) * CH + n], Wa3[(k0 + 1) * CH + n]));
        out3[j * 2 + 1] = h2u(__floats2half2_rn(Wa3[(k0 + 8) * CH + n], Wa3[(k0 + 9) * CH + n]));
    }
    ((uint4*)g_Wt2)[p] = make_uint4(out2[0], out2[1], out2[2], out2[3]);
    ((uint4*)g_Wt3)[p] = make_uint4(out3[0], out3[1], out3[2], out3[3]);
}

// ---------------- CSR build ----------------
__global__ void hist_kernel(const int* __restrict__ dst) {
    int i = blockIdx.x * blockDim.x + threadIdx.x;
    if (i < N_EDGES) atomicAdd(&g_deg[dst[i]], 1);
}

// phase 1: per-1024-chunk inclusive scan (parallel over chunks)
__global__ void scan1_kernel() {
    __shared__ int wsum[32];
    int b = blockIdx.x, tid = threadIdx.x;
    int wid = tid >> 5, lane = tid & 31;
    int i = b * 1024 + tid;
    int v = (i < N_NODES) ? g_deg[i] : 0;
    if (i < N_NODES) g_deginv[i] = (v > 0) ? (1.0f / (float)v) : 0.0f;

    int incl = warp_incl_scan(v, lane);
    if (lane == 31) wsum[wid] = incl;
    __syncthreads();
    if (wid == 0) {
        int ws = wsum[lane];
        int wi = warp_incl_scan(ws, lane);
        wsum[lane] = wi - ws;   // exclusive warp prefix
    }
    __syncthreads();
    int inclusive = wsum[wid] + incl;
    if (i < N_NODES) g_off[i + 1] = inclusive;      // chunk-local inclusive
    if (tid == 1023) g_chunksum[b] = inclusive;     // chunk total
}

// phase 2: scan the 98 chunk sums
__global__ void scan2_kernel() {
    __shared__ int ws[4];
    int tid = threadIdx.x, wid = tid >> 5, lane = tid & 31;
    int v = (tid < NCHUNK) ? g_chunksum[tid] : 0;
    int incl = warp_incl_scan(v, lane);
    if (lane == 31) ws[wid] = incl;
    __syncthreads();
    int woff = 0;
    #pragma unroll
    for (int w = 0; w < 4; w++) if (w < wid) woff += ws[w];
    if (tid < NCHUNK) g_chunkoff[tid] = woff + incl - v;   // exclusive chunk offset
}

// phase 3: add chunk offsets back, produce g_off / g_cur
__global__ void scan3_kernel() {
    int b = blockIdx.x, tid = threadIdx.x;
    int i = b * 1024 + tid;
    if (i < N_NODES) {
        int incl = g_off[i + 1] + g_chunkoff[b];
        g_off[i + 1] = incl;
        g_cur[i]     = incl - g_deg[i];
        if (i == 0) g_off[0] = 0;
    }
}

__global__ void fill_kernel(const int* __restrict__ src, const int* __restrict__ dst) {
    int i = blockIdx.x * blockDim.x + threadIdx.x;
    if (i < N_EDGES) {
        int d   = dst[i];
        int pos = atomicAdd(&g_cur[d], 1);
        g_col[pos] = src[i];
    }
}

// ---------------- layer 1 (K = 3, exact fp32) ----------------
__global__ void layer1_kernel(const float* __restrict__ x,
                              const float* __restrict__ Wl,
                              const float* __restrict__ Wr,
                              const float* __restrict__ b,
                              float* __restrict__ hout) {
    __shared__ float aggx[64][4];
    __shared__ float xs[64][4];
    int tid  = threadIdx.x;
    int warp = tid >> 5, lane = tid & 31;
    int base = blockIdx.x * 64;

    for (int n = warp; n < 64; n += 4) {
        int node = base + n;
        if (node >= N_NODES) break;
        int s0 = g_off[node], e0 = g_off[node + 1];
        float a0 = 0.f, a1 = 0.f, a2 = 0.f;
        for (int idx = s0 + lane; idx < e0; idx += 32) {
            int j = g_col[idx];
            a0 += x[j * 3 + 0];
            a1 += x[j * 3 + 1];
            a2 += x[j * 3 + 2];
        }
        #pragma unroll
        for (int o = 16; o > 0; o >>= 1) {
            a0 += __shfl_xor_sync(0xffffffffu, a0, o);
            a1 += __shfl_xor_sync(0xffffffffu, a1, o);
            a2 += __shfl_xor_sync(0xffffffffu, a2, o);
        }
        if (lane == 0) {
            float di = g_deginv[node];
            aggx[n][0] = a0 * di; aggx[n][1] = a1 * di; aggx[n][2] = a2 * di;
            xs[n][0] = x[node * 3 + 0];
            xs[n][1] = x[node * 3 + 1];
            xs[n][2] = x[node * 3 + 2];
        }
    }
    __syncthreads();

    int t = tid;
    float wl0 = Wl[0 * CH + t], wl1 = Wl[1 * CH + t], wl2 = Wl[2 * CH + t];
    float wr0 = Wr[0 * CH + t], wr1 = Wr[1 * CH + t], wr2 = Wr[2 * CH + t];
    float bb  = b[t];
    for (int n = 0; n < 64; n++) {
        int node = base + n;
        if (node >= N_NODES) break;
        float acc = bb;
        acc += aggx[n][0] * wl0 + aggx[n][1] * wl1 + aggx[n][2] * wl2;
        acc += xs[n][0]   * wr0 + xs[n][1]   * wr1 + xs[n][2]   * wr2;
        hout[(size_t)node * CH + t] = fmaxf(acc, 0.0f);
    }
}

// ---------------- layers 2/3: split-K two-pass fp16 tensor-core GEMM ----------------
// Pass 0: As = agg (K 0..127) vs Wl; pass 1: As = own vs Wr; same fp32 accumulators.
// 8 warps = 2(M) x 4(N); warp tile 32x32. A tile fp16: 64 x 68 half2 = 17.4 KB smem.
__global__ void __launch_bounds__(256, 4)
layerTC_kernel(const float* __restrict__ hin, float* __restrict__ hout,
               const __half* __restrict__ Wt, const float* __restrict__ bias) {
    __shared__ __align__(16) unsigned As[NPB * AS_H2];   // half2 elements

    int tid  = threadIdx.x;
    int warp = tid >> 5, lane = tid & 31;
    int base = blockIdx.x * NPB;

    int wm = warp >> 2;          // 0..1  -> M rows [wm*32, wm*32+32)
    int wn = warp & 3;           // 0..3  -> N cols [wn*32, wn*32+32)
    int gid = lane >> 2, tig = lane & 3;

    float acc[2][4][4];
    #pragma unroll
    for (int mt = 0; mt < 2; mt++)
        #pragma unroll
        for (int nt = 0; nt < 4; nt++)
            #pragma unroll
            for (int r = 0; r < 4; r++) acc[mt][nt][r] = 0.0f;

    const uint4* Wf = (const uint4*)Wt;

    #pragma unroll
    for (int pass = 0; pass < 2; pass++) {
        // ---- Phase A: fill As with agg (pass 0) or own rows (pass 1), fp16 ----
        if (pass == 0) {
            for (int n = warp; n < NPB; n += 8) {
                int node = base + n;
                if (node >= N_NODES) break;      // tail block
                int s0 = g_off[node], e0 = g_off[node + 1];
                float4 A0 = make_float4(0.f, 0.f, 0.f, 0.f);
                float4 A1 = A0, A2 = A0, A3 = A0;
                int idx = s0;
                for (; idx + 4 <= e0; idx += 4) {
                    int j0 = g_col[idx + 0], j1 = g_col[idx + 1];
                    int j2 = g_col[idx + 2], j3 = g_col[idx + 3];
                    float4 v0 = *(const float4*)&hin[(size_t)j0 * CH + lane * 4];
                    float4 v1 = *(const float4*)&hin[(size_t)j1 * CH + lane * 4];
                    float4 v2 = *(const float4*)&hin[(size_t)j2 * CH + lane * 4];
                    float4 v3 = *(const float4*)&hin[(size_t)j3 * CH + lane * 4];
                    A0.x += v0.x; A0.y += v0.y; A0.z += v0.z; A0.w += v0.w;
                    A1.x += v1.x; A1.y += v1.y; A1.z += v1.z; A1.w += v1.w;
                    A2.x += v2.x; A2.y += v2.y; A2.z += v2.z; A2.w += v2.w;
                    A3.x += v3.x; A3.y += v3.y; A3.z += v3.z; A3.w += v3.w;
                }
                for (; idx < e0; idx++) {
                    int j = g_col[idx];
                    float4 v = *(const float4*)&hin[(size_t)j * CH + lane * 4];
                    A0.x += v.x; A0.y += v.y; A0.z += v.z; A0.w += v.w;
                }
                float di = g_deginv[node];
                float ax = ((A0.x + A1.x) + (A2.x + A3.x)) * di;
                float ay = ((A0.y + A1.y) + (A2.y + A3.y)) * di;
                float az = ((A0.z + A1.z) + (A2.z + A3.z)) * di;
                float aw = ((A0.w + A1.w) + (A2.w + A3.w)) * di;
                uint2 st;
                st.x = h2u(__floats2half2_rn(ax, ay));
                st.y = h2u(__floats2half2_rn(az, aw));
                *(uint2*)&As[n * AS_H2 + lane * 2] = st;
            }
        } else {
            for (int n = warp; n < NPB; n += 8) {
                int node = base + n;
                if (node >= N_NODES) break;
                float4 own = *(const float4*)&hin[(size_t)node * CH + lane * 4];
                uint2 st;
                st.x = h2u(__floats2half2_rn(own.x, own.y));
                st.y = h2u(__floats2half2_rn(own.z, own.w));
                *(uint2*)&As[n * AS_H2 + lane * 2] = st;
            }
        }
        __syncthreads();

        // ---- Phase B: accumulate (64x128) @ (128x128) via m16n8k16 fp16 ----
        #pragma unroll
        for (int kt = 0; kt < 8; kt++) {
            unsigned i0 = ((((unsigned)(wn * 2 + pass) * 8 + kt) * 2) * 32) + lane;
            uint4 q0 = Wf[i0];        // nt 0,1
            uint4 q1 = Wf[i0 + 32];   // nt 2,3
            unsigned bfr[4][2] = {
                { q0.x, q0.y }, { q0.z, q0.w },
                { q1.x, q1.y }, { q1.z, q1.w } };

            unsigned kc = kt * 8;     // half2 column base within row
            #pragma unroll
            for (int mt = 0; mt < 2; mt++) {
                unsigned r0 = (unsigned)(wm * 32 + mt * 16 + gid) * AS_H2 + kc + tig;
                unsigned a[4];
                a[0] = As[r0];
                a[1] = As[r0 + 8 * AS_H2];
                a[2] = As[r0 + 4];
                a[3] = As[r0 + 8 * AS_H2 + 4];
                #pragma unroll
                for (int nt = 0; nt < 4; nt++)
                    mma_f16(acc[mt][nt], a, bfr[nt]);
            }
        }
        __syncthreads();   // pass-1 Phase A must not overwrite before all reads done
    }

    // ---- epilogue: bias + relu + store (float2, cols adjacent) ----
    #pragma unroll
    for (int nt = 0; nt < 4; nt++) {
        int col = wn * 32 + nt * 8 + tig * 2;
        float bb0 = bias[col], bb1 = bias[col + 1];
        #pragma unroll
        for (int mt = 0; mt < 2; mt++) {
            int row = base + wm * 32 + mt * 16 + gid;
            if (row < N_NODES) {
                float2 v;
                v.x = fmaxf(acc[mt][nt][0] + bb0, 0.0f);
                v.y = fmaxf(acc[mt][nt][1] + bb1, 0.0f);
                *(float2*)&hout[(size_t)row * CH + col] = v;
            }
            if (row + 8 < N_NODES) {
                float2 v;
                v.x = fmaxf(acc[mt][nt][2] + bb0, 0.0f);
                v.y = fmaxf(acc[mt][nt][3] + bb1, 0.0f);
                *(float2*)&hout[(size_t)(row + 8) * CH + col] = v;
            }
        }
    }
}

// ---------------- launch ----------------
extern "C" void kernel_launch(void* const* d_in, const int* in_sizes, int n_in,
                              void* d_out, int out_size) {
    const float* x   = (const float*)d_in[0];
    const int*   ei  = (const int*)d_in[1];      // [2, E]
    const float* W1l = (const float*)d_in[2];
    const float* W1r = (const float*)d_in[3];
    const float* b1  = (const float*)d_in[4];
    const float* W2l = (const float*)d_in[5];
    const float* W2r = (const float*)d_in[6];
    const float* b2  = (const float*)d_in[7];
    const float* W3l = (const float*)d_in[8];
    const float* W3r = (const float*)d_in[9];
    const float* b3  = (const float*)d_in[10];
    float* out = (float*)d_out;

    const int* src = ei;
    const int* dst = ei + N_EDGES;

    float* h1; float* h2; __half* Wt2; __half* Wt3; int* degp;
    cudaGetSymbolAddress((void**)&h1, g_h1);
    cudaGetSymbolAddress((void**)&h2, g_h2);
    cudaGetSymbolAddress((void**)&Wt2, g_Wt2);
    cudaGetSymbolAddress((void**)&Wt3, g_Wt3);
    cudaGetSymbolAddress((void**)&degp, g_deg);

    // weight prep + CSR build
    prep_kernel<<<(4096 + 255) / 256, 256>>>(W2l, W2r, W3l, W3r);
    cudaMemsetAsync(degp, 0, N_NODES * sizeof(int));
    hist_kernel<<<(N_EDGES + 255) / 256, 256>>>(dst);
    scan1_kernel<<<NCHUNK, 1024>>>();
    scan2_kernel<<<1, 128>>>();
    scan3_kernel<<<NCHUNK, 1024>>>();
    fill_kernel<<<(N_EDGES + 255) / 256, 256>>>(src, dst);

    // layers
    layer1_kernel<<<(N_NODES + 63) / 64, 128>>>(x, W1l, W1r, b1, h1);
    layerTC_kernel<<<NBLK, 256>>>(h1, h2, Wt2, b2);
    layerTC_kernel<<<NBLK, 256>>>(h2, out, Wt3, b3);
}

// round 11
// speedup vs baseline: 1.4870x; 1.0825x over previous
#include <cuda_runtime.h>
#include <cuda_fp16.h>
#include <cstdint>

#define N_NODES 100000
#define N_EDGES 600000
#define CH 128
#define NPB 64            // nodes per block tile (tail block handles 32)
#define NBLK 1563         // ceil(100000/64)
#define NCHUNK 98         // ceil(100000/1024)
#define AS_H2 68          // half2 per row: 64 + 4 pad -> conflict-free fragment LDS

// ---------------- scratch (static device globals; no allocation) ----------------
__device__ int    g_deg[N_NODES];
__device__ float  g_deginv[N_NODES];
__device__ int    g_off[N_NODES + 1];
__device__ int    g_cur[N_NODES];
__device__ int    g_col[N_EDGES];
__device__ int    g_chunksum[NCHUNK];
__device__ int    g_chunkoff[NCHUNK];
__device__ __align__(16) __half g_h1[(size_t)N_NODES * CH];
__device__ __align__(16) __half g_h2[(size_t)N_NODES * CH];
// fp16 fragment-ordered weights: uint4 idx = ((((wn*2+pass)*8 + kt)*2 + g)*32 + lane)
__device__ __align__(16) __half g_Wt2[128 * 256];
__device__ __align__(16) __half g_Wt3[128 * 256];

// ---------------- helpers ----------------
__device__ __forceinline__ int warp_incl_scan(int v, int lane) {
    #pragma unroll
    for (int o = 1; o < 32; o <<= 1) {
        int t = __shfl_up_sync(0xffffffffu, v, o);
        if (lane >= o) v += t;
    }
    return v;
}
__device__ __forceinline__ void mma_f16(float* c, const unsigned* a, const unsigned* b) {
    asm volatile(
        "mma.sync.aligned.m16n8k16.row.col.f32.f16.f16.f32 "
        "{%0,%1,%2,%3}, {%4,%5,%6,%7}, {%8,%9}, {%0,%1,%2,%3};"
        : "+f"(c[0]), "+f"(c[1]), "+f"(c[2]), "+f"(c[3])
        : "r"(a[0]), "r"(a[1]), "r"(a[2]), "r"(a[3]), "r"(b[0]), "r"(b[1]));
}
__device__ __forceinline__ unsigned h2u(__half2 h) {
    return *reinterpret_cast<unsigned*>(&h);
}
__device__ __forceinline__ void acc4_h2(float4& A, uint2 v) {
    float2 lo = __half22float2(*reinterpret_cast<__half2*>(&v.x));
    float2 hi = __half22float2(*reinterpret_cast<__half2*>(&v.y));
    A.x += lo.x; A.y += lo.y; A.z += hi.x; A.w += hi.y;
}

// ---------------- weight prep: fp16 fragment-order shuffle + split-K ----------------
__global__ void prep_kernel(const float* __restrict__ W2l, const float* __restrict__ W2r,
                            const float* __restrict__ W3l, const float* __restrict__ W3r) {
    int p = blockIdx.x * blockDim.x + threadIdx.x;   // 4096 uint4
    if (p >= 4096) return;
    int lane = p & 31;
    int g    = (p >> 5) & 1;
    int kt   = (p >> 6) & 7;
    int pass = (p >> 9) & 1;
    int wn   = (p >> 10) & 3;
    int gid = lane >> 2, tig = lane & 3;
    int k0 = kt * 16 + tig * 2;

    const float* Wa2 = pass ? W2r : W2l;
    const float* Wa3 = pass ? W3r : W3l;

    unsigned out2[4], out3[4];
    #pragma unroll
    for (int j = 0; j < 2; j++) {
        int n = wn * 32 + (g * 2 + j) * 8 + gid;
        out2[j * 2 + 0] = h2u(__floats2half2_rn(Wa2[(k0 + 0) * CH + n], Wa2[(k0 + 1) * CH + n]));
        out2[j * 2 + 1] = h2u(__floats2half2_rn(Wa2[(k0 + 8) * CH + n], Wa2[(k0 + 9) * CH + n]));
        out3[j * 2 + 0] = h2u(__floats2half2_rn(Wa3[(k0 + 0) * CH + n], Wa3[(k0 + 1) * CH + n]));
        out3[j * 2 + 1] = h2u(__floats2half2_rn(Wa3[(k0 + 8) * CH + n], Wa3[(k0 + 9) * CH + n]));
    }
    ((uint4*)g_Wt2)[p] = make_uint4(out2[0], out2[1], out2[2], out2[3]);
    ((uint4*)g_Wt3)[p] = make_uint4(out3[0], out3[1], out3[2], out3[3]);
}

// ---------------- CSR build ----------------
__global__ void hist_kernel(const int* __restrict__ dst) {
    int i = blockIdx.x * blockDim.x + threadIdx.x;
    if (i < N_EDGES) atomicAdd(&g_deg[dst[i]], 1);
}

__global__ void scan1_kernel() {
    __shared__ int wsum[32];
    int b = blockIdx.x, tid = threadIdx.x;
    int wid = tid >> 5, lane = tid & 31;
    int i = b * 1024 + tid;
    int v = (i < N_NODES) ? g_deg[i] : 0;
    if (i < N_NODES) g_deginv[i] = (v > 0) ? (1.0f / (float)v) : 0.0f;

    int incl = warp_incl_scan(v, lane);
    if (lane == 31) wsum[wid] = incl;
    __syncthreads();
    if (wid == 0) {
        int ws = wsum[lane];
        int wi = warp_incl_scan(ws, lane);
        wsum[lane] = wi - ws;   // exclusive warp prefix
    }
    __syncthreads();
    int inclusive = wsum[wid] + incl;
    if (i < N_NODES) g_off[i + 1] = inclusive;      // chunk-local inclusive
    if (tid == 1023) g_chunksum[b] = inclusive;     // chunk total
}

__global__ void scan2_kernel() {
    __shared__ int ws[4];
    int tid = threadIdx.x, wid = tid >> 5, lane = tid & 31;
    int v = (tid < NCHUNK) ? g_chunksum[tid] : 0;
    int incl = warp_incl_scan(v, lane);
    if (lane == 31) ws[wid] = incl;
    __syncthreads();
    int woff = 0;
    #pragma unroll
    for (int w = 0; w < 4; w++) if (w < wid) woff += ws[w];
    if (tid < NCHUNK) g_chunkoff[tid] = woff + incl - v;   // exclusive chunk offset
}

__global__ void scan3_kernel() {
    int b = blockIdx.x, tid = threadIdx.x;
    int i = b * 1024 + tid;
    if (i < N_NODES) {
        int incl = g_off[i + 1] + g_chunkoff[b];
        g_off[i + 1] = incl;
        g_cur[i]     = incl - g_deg[i];
        if (i == 0) g_off[0] = 0;
    }
}

__global__ void fill_kernel(const int* __restrict__ src, const int* __restrict__ dst) {
    int i = blockIdx.x * blockDim.x + threadIdx.x;
    if (i < N_EDGES) {
        int d   = dst[i];
        int pos = atomicAdd(&g_cur[d], 1);
        g_col[pos] = src[i];
    }
}

// ---------------- layer 1 (K = 3, fp32 math, fp16 output) ----------------
__global__ void layer1_kernel(const float* __restrict__ x,
                              const float* __restrict__ Wl,
                              const float* __restrict__ Wr,
                              const float* __restrict__ b,
                              __half* __restrict__ hout) {
    __shared__ float aggx[64][4];
    __shared__ float xs[64][4];
    int tid  = threadIdx.x;
    int warp = tid >> 5, lane = tid & 31;
    int base = blockIdx.x * 64;

    for (int n = warp; n < 64; n += 4) {
        int node = base + n;
        if (node >= N_NODES) break;
        int s0 = g_off[node], e0 = g_off[node + 1];
        float a0 = 0.f, a1 = 0.f, a2 = 0.f;
        for (int idx = s0 + lane; idx < e0; idx += 32) {
            int j = g_col[idx];
            a0 += x[j * 3 + 0];
            a1 += x[j * 3 + 1];
            a2 += x[j * 3 + 2];
        }
        #pragma unroll
        for (int o = 16; o > 0; o >>= 1) {
            a0 += __shfl_xor_sync(0xffffffffu, a0, o);
            a1 += __shfl_xor_sync(0xffffffffu, a1, o);
            a2 += __shfl_xor_sync(0xffffffffu, a2, o);
        }
        if (lane == 0) {
            float di = g_deginv[node];
            aggx[n][0] = a0 * di; aggx[n][1] = a1 * di; aggx[n][2] = a2 * di;
            xs[n][0] = x[node * 3 + 0];
            xs[n][1] = x[node * 3 + 1];
            xs[n][2] = x[node * 3 + 2];
        }
    }
    __syncthreads();

    int t = tid;
    float wl0 = Wl[0 * CH + t], wl1 = Wl[1 * CH + t], wl2 = Wl[2 * CH + t];
    float wr0 = Wr[0 * CH + t], wr1 = Wr[1 * CH + t], wr2 = Wr[2 * CH + t];
    float bb  = b[t];
    for (int n = 0; n < 64; n++) {
        int node = base + n;
        if (node >= N_NODES) break;
        float acc = bb;
        acc += aggx[n][0] * wl0 + aggx[n][1] * wl1 + aggx[n][2] * wl2;
        acc += xs[n][0]   * wr0 + xs[n][1]   * wr1 + xs[n][2]   * wr2;
        hout[(size_t)node * CH + t] = __float2half(fmaxf(acc, 0.0f));
    }
}

// ---------------- layers 2/3: split-K two-pass fp16 TC GEMM, fp16 feature I/O ----------------
// Pass 0: As = agg (fp16 gather, fp32 accum) vs Wl; pass 1: As = own rows vs Wr.
// 8 warps = 2(M) x 4(N); warp tile 32x32. HALF_OUT: write fp16 (hidden) or fp32 (final).
template <bool HALF_OUT>
__global__ void __launch_bounds__(256, 4)
layerTC_kernel(const __half* __restrict__ hin, void* __restrict__ hout_v,
               const __half* __restrict__ Wt, const float* __restrict__ bias) {
    __shared__ __align__(16) unsigned As[NPB * AS_H2];   // half2 elements

    int tid  = threadIdx.x;
    int warp = tid >> 5, lane = tid & 31;
    int base = blockIdx.x * NPB;

    int wm = warp >> 2;          // 0..1  -> M rows [wm*32, wm*32+32)
    int wn = warp & 3;           // 0..3  -> N cols [wn*32, wn*32+32)
    int gid = lane >> 2, tig = lane & 3;

    float acc[2][4][4];
    #pragma unroll
    for (int mt = 0; mt < 2; mt++)
        #pragma unroll
        for (int nt = 0; nt < 4; nt++)
            #pragma unroll
            for (int r = 0; r < 4; r++) acc[mt][nt][r] = 0.0f;

    const uint4* Wf = (const uint4*)Wt;

    #pragma unroll
    for (int pass = 0; pass < 2; pass++) {
        // ---- Phase A ----
        if (pass == 0) {
            for (int n = warp; n < NPB; n += 8) {
                int node = base + n;
                if (node >= N_NODES) break;      // tail block
                int s0 = g_off[node], e0 = g_off[node + 1];
                float4 A0 = make_float4(0.f, 0.f, 0.f, 0.f);
                float4 A1 = A0, A2 = A0, A3 = A0;
                int idx = s0;
                for (; idx + 4 <= e0; idx += 4) {
                    int j0 = g_col[idx + 0], j1 = g_col[idx + 1];
                    int j2 = g_col[idx + 2], j3 = g_col[idx + 3];
                    uint2 v0 = *(const uint2*)&hin[(size_t)j0 * CH + lane * 4];
                    uint2 v1 = *(const uint2*)&hin[(size_t)j1 * CH + lane * 4];
                    uint2 v2 = *(const uint2*)&hin[(size_t)j2 * CH + lane * 4];
                    uint2 v3 = *(const uint2*)&hin[(size_t)j3 * CH + lane * 4];
                    acc4_h2(A0, v0);
                    acc4_h2(A1, v1);
                    acc4_h2(A2, v2);
                    acc4_h2(A3, v3);
                }
                for (; idx < e0; idx++) {
                    int j = g_col[idx];
                    uint2 v = *(const uint2*)&hin[(size_t)j * CH + lane * 4];
                    acc4_h2(A0, v);
                }
                float di = g_deginv[node];
                float ax = ((A0.x + A1.x) + (A2.x + A3.x)) * di;
                float ay = ((A0.y + A1.y) + (A2.y + A3.y)) * di;
                float az = ((A0.z + A1.z) + (A2.z + A3.z)) * di;
                float aw = ((A0.w + A1.w) + (A2.w + A3.w)) * di;
                uint2 st;
                st.x = h2u(__floats2half2_rn(ax, ay));
                st.y = h2u(__floats2half2_rn(az, aw));
                *(uint2*)&As[n * AS_H2 + lane * 2] = st;
            }
        } else {
            for (int n = warp; n < NPB; n += 8) {
                int node = base + n;
                if (node >= N_NODES) break;
                // straight bit-copy: input already fp16
                uint2 own = *(const uint2*)&hin[(size_t)node * CH + lane * 4];
                *(uint2*)&As[n * AS_H2 + lane * 2] = own;
            }
        }
        __syncthreads();

        // ---- Phase B: accumulate (64x128) @ (128x128) via m16n8k16 fp16 ----
        #pragma unroll
        for (int kt = 0; kt < 8; kt++) {
            unsigned i0 = ((((unsigned)(wn * 2 + pass) * 8 + kt) * 2) * 32) + lane;
            uint4 q0 = Wf[i0];        // nt 0,1
            uint4 q1 = Wf[i0 + 32];   // nt 2,3
            unsigned bfr[4][2] = {
                { q0.x, q0.y }, { q0.z, q0.w },
                { q1.x, q1.y }, { q1.z, q1.w } };

            unsigned kc = kt * 8;     // half2 column base within row
            #pragma unroll
            for (int mt = 0; mt < 2; mt++) {
                unsigned r0 = (unsigned)(wm * 32 + mt * 16 + gid) * AS_H2 + kc + tig;
                unsigned a[4];
                a[0] = As[r0];
                a[1] = As[r0 + 8 * AS_H2];
                a[2] = As[r0 + 4];
                a[3] = As[r0 + 8 * AS_H2 + 4];
                #pragma unroll
                for (int nt = 0; nt < 4; nt++)
                    mma_f16(acc[mt][nt], a, bfr[nt]);
            }
        }
        __syncthreads();   // pass-1 Phase A must not overwrite before all reads done
    }

    // ---- epilogue: bias + relu + store ----
    #pragma unroll
    for (int nt = 0; nt < 4; nt++) {
        int col = wn * 32 + nt * 8 + tig * 2;
        float bb0 = bias[col], bb1 = bias[col + 1];
        #pragma unroll
        for (int mt = 0; mt < 2; mt++) {
            int row = base + wm * 32 + mt * 16 + gid;
            #pragma unroll
            for (int half_row = 0; half_row < 2; half_row++) {
                int r = row + half_row * 8;
                if (r >= N_NODES) continue;
                float vx = fmaxf(acc[mt][nt][half_row * 2 + 0] + bb0, 0.0f);
                float vy = fmaxf(acc[mt][nt][half_row * 2 + 1] + bb1, 0.0f);
                if (HALF_OUT) {
                    __half* ho = (__half*)hout_v;
                    __half2 hv = __floats2half2_rn(vx, vy);
                    *(__half2*)&ho[(size_t)r * CH + col] = hv;
                } else {
                    float* fo = (float*)hout_v;
                    float2 fv = make_float2(vx, vy);
                    *(float2*)&fo[(size_t)r * CH + col] = fv;
                }
            }
        }
    }
}

// ---------------- launch ----------------
extern "C" void kernel_launch(void* const* d_in, const int* in_sizes, int n_in,
                              void* d_out, int out_size) {
    const float* x   = (const float*)d_in[0];
    const int*   ei  = (const int*)d_in[1];      // [2, E]
    const float* W1l = (const float*)d_in[2];
    const float* W1r = (const float*)d_in[3];
    const float* b1  = (const float*)d_in[4];
    const float* W2l = (const float*)d_in[5];
    const float* W2r = (const float*)d_in[6];
    const float* b2  = (const float*)d_in[7];
    const float* W3l = (const float*)d_in[8];
    const float* W3r = (const float*)d_in[9];
    const float* b3  = (const float*)d_in[10];
    float* out = (float*)d_out;

    const int* src = ei;
    const int* dst = ei + N_EDGES;

    __half* h1; __half* h2; __half* Wt2; __half* Wt3; int* degp;
    cudaGetSymbolAddress((void**)&h1, g_h1);
    cudaGetSymbolAddress((void**)&h2, g_h2);
    cudaGetSymbolAddress((void**)&Wt2, g_Wt2);
    cudaGetSymbolAddress((void**)&Wt3, g_Wt3);
    cudaGetSymbolAddress((void**)&degp, g_deg);

    // weight prep + CSR build
    prep_kernel<<<(4096 + 255) / 256, 256>>>(W2l, W2r, W3l, W3r);
    cudaMemsetAsync(degp, 0, N_NODES * sizeof(int));
    hist_kernel<<<(N_EDGES + 255) / 256, 256>>>(dst);
    scan1_kernel<<<NCHUNK, 1024>>>();
    scan2_kernel<<<1, 128>>>();
    scan3_kernel<<<NCHUNK, 1024>>>();
    fill_kernel<<<(N_EDGES + 255) / 256, 256>>>(src, dst);

    // layers
    layer1_kernel<<<(N_NODES + 63) / 64, 128>>>(x, W1l, W1r, b1, h1);
    layerTC_kernel<true><<<NBLK, 256>>>(h1, (void*)h2, Wt2, b2);
    layerTC_kernel<false><<<NBLK, 256>>>(h2, (void*)out, Wt3, b3);
}

// round 12
// speedup vs baseline: 1.5215x; 1.0232x over previous
#include <cuda_runtime.h>
#include <cuda_fp16.h>
#include <cstdint>

#define N_NODES 100000
#define N_EDGES 600000
#define CH 128
#define NPB 64            // nodes per block tile (tail block handles 32)
#define NBLK 1563         // ceil(100000/64)
#define NCHUNK 98         // ceil(100000/1024)
#define AS_H2 68          // half2 per row: 64 + 4 pad -> conflict-free fragment LDS
#define PREP_BLOCKS 16    // 4096 uint4 / 256
#define ZCOUNT (N_NODES + 2 * NCHUNK)   // deg + lookback words, one memset

// ---------------- scratch (static device globals; no allocation) ----------------
__device__ __align__(16) int g_zeroed[ZCOUNT];   // [0,N): deg; [N, N+2*NCHUNK): lookback u64
__device__ float  g_deginv[N_NODES];
__device__ int    g_off[N_NODES + 1];
__device__ int    g_cur[N_NODES];
__device__ int    g_col[N_EDGES];
__device__ __align__(16) __half g_h1[(size_t)N_NODES * CH];
__device__ __align__(16) __half g_h2[(size_t)N_NODES * CH];
// fp16 fragment-ordered weights: uint4 idx = ((((wn*2+pass)*8 + kt)*2 + g)*32 + lane)
__device__ __align__(16) __half g_Wt2[128 * 256];
__device__ __align__(16) __half g_Wt3[128 * 256];

// ---------------- helpers ----------------
__device__ __forceinline__ int warp_incl_scan(int v, int lane) {
    #pragma unroll
    for (int o = 1; o < 32; o <<= 1) {
        int t = __shfl_up_sync(0xffffffffu, v, o);
        if (lane >= o) v += t;
    }
    return v;
}
__device__ __forceinline__ void mma_f16(float* c, const unsigned* a, const unsigned* b) {
    asm volatile(
        "mma.sync.aligned.m16n8k16.row.col.f32.f16.f16.f32 "
        "{%0,%1,%2,%3}, {%4,%5,%6,%7}, {%8,%9}, {%0,%1,%2,%3};"
        : "+f"(c[0]), "+f"(c[1]), "+f"(c[2]), "+f"(c[3])
        : "r"(a[0]), "r"(a[1]), "r"(a[2]), "r"(a[3]), "r"(b[0]), "r"(b[1]));
}
__device__ __forceinline__ unsigned h2u(__half2 h) {
    return *reinterpret_cast<unsigned*>(&h);
}
__device__ __forceinline__ void acc4_h2(float4& A, uint2 v) {
    float2 lo = __half22float2(*reinterpret_cast<__half2*>(&v.x));
    float2 hi = __half22float2(*reinterpret_cast<__half2*>(&v.y));
    A.x += lo.x; A.y += lo.y; A.z += hi.x; A.w += hi.y;
}

// ---------------- fused prep (16 blocks) + degree histogram (rest) ----------------
__global__ void histprep_kernel(const int* __restrict__ dst,
                                const float* __restrict__ W2l, const float* __restrict__ W2r,
                                const float* __restrict__ W3l, const float* __restrict__ W3r) {
    if (blockIdx.x < PREP_BLOCKS) {
        int p = blockIdx.x * blockDim.x + threadIdx.x;   // 4096 uint4
        if (p >= 4096) return;
        int lane = p & 31;
        int g    = (p >> 5) & 1;
        int kt   = (p >> 6) & 7;
        int pass = (p >> 9) & 1;
        int wn   = (p >> 10) & 3;
        int gid = lane >> 2, tig = lane & 3;
        int k0 = kt * 16 + tig * 2;

        const float* Wa2 = pass ? W2r : W2l;
        const float* Wa3 = pass ? W3r : W3l;

        unsigned out2[4], out3[4];
        #pragma unroll
        for (int j = 0; j < 2; j++) {
            int n = wn * 32 + (g * 2 + j) * 8 + gid;
            out2[j * 2 + 0] = h2u(__floats2half2_rn(Wa2[(k0 + 0) * CH + n], Wa2[(k0 + 1) * CH + n]));
            out2[j * 2 + 1] = h2u(__floats2half2_rn(Wa2[(k0 + 8) * CH + n], Wa2[(k0 + 9) * CH + n]));
            out3[j * 2 + 0] = h2u(__floats2half2_rn(Wa3[(k0 + 0) * CH + n], Wa3[(k0 + 1) * CH + n]));
            out3[j * 2 + 1] = h2u(__floats2half2_rn(Wa3[(k0 + 8) * CH + n], Wa3[(k0 + 9) * CH + n]));
        }
        ((uint4*)g_Wt2)[p] = make_uint4(out2[0], out2[1], out2[2], out2[3]);
        ((uint4*)g_Wt3)[p] = make_uint4(out3[0], out3[1], out3[2], out3[3]);
    } else {
        int i = (blockIdx.x - PREP_BLOCKS) * blockDim.x + threadIdx.x;
        if (i < N_EDGES) atomicAdd(&g_zeroed[dst[i]], 1);
    }
}

// ---------------- single-pass decoupled-lookback scan ----------------
// look[b] (u64, zeroed per call): flag in [63:32] (0 invalid, 1 agg, 2 inclusive), value in [31:0].
__global__ void __launch_bounds__(1024, 1)
scanlb_kernel() {
    __shared__ int wsum[32];
    __shared__ int sh_excl;
    volatile unsigned long long* look =
        (volatile unsigned long long*)(g_zeroed + N_NODES);

    int b = blockIdx.x, tid = threadIdx.x;
    int wid = tid >> 5, lane = tid & 31;
    int i = b * 1024 + tid;
    int v = (i < N_NODES) ? g_zeroed[i] : 0;

    int incl = warp_incl_scan(v, lane);
    if (lane == 31) wsum[wid] = incl;
    __syncthreads();

    if (wid == 0) {
        int ws = wsum[lane];
        int wi = warp_incl_scan(ws, lane);
        wsum[lane] = wi - ws;                     // exclusive warp prefix
        int tot = __shfl_sync(0xffffffffu, wi, 31);

        // publish aggregate (block 0 publishes inclusive directly)
        if (lane == 0)
            look[b] = ((unsigned long long)(b == 0 ? 2u : 1u) << 32) | (unsigned)tot;

        // warp-parallel lookback
        int excl = 0;
        if (b > 0) {
            int win = b - 1;
            while (true) {
                int j = win - lane;
                unsigned long long s = 0;
                if (j >= 0) {
                    do { s = look[j]; } while ((unsigned)(s >> 32) == 0u);
                }
                unsigned flag = (j >= 0) ? (unsigned)(s >> 32) : 0u;
                int val = (int)(unsigned)s;
                unsigned mask = __ballot_sync(0xffffffffu, flag == 2u);
                int contrib;
                if (mask) {
                    int lz = __ffs(mask) - 1;     // nearest predecessor with inclusive
                    contrib = (lane <= lz && j >= 0) ? val : 0;
                } else {
                    contrib = (j >= 0) ? val : 0;
                }
                #pragma unroll
                for (int o = 16; o > 0; o >>= 1)
                    contrib += __shfl_xor_sync(0xffffffffu, contrib, o);
                excl += contrib;
                if (mask) break;
                win -= 32;
            }
            // publish inclusive for successors ASAP
            if (lane == 0)
                look[b] = (2ULL << 32) | (unsigned)(excl + tot);
        }
        if (lane == 0) sh_excl = excl;
    }
    __syncthreads();

    int inclusive = sh_excl + wsum[wid] + incl;
    if (i < N_NODES) {
        g_off[i + 1]  = inclusive;
        g_cur[i]      = inclusive - v;            // exclusive offset = fill cursor
        g_deginv[i]   = (v > 0) ? (1.0f / (float)v) : 0.0f;
        if (i == 0) g_off[0] = 0;
    }
}

__global__ void fill_kernel(const int* __restrict__ src, const int* __restrict__ dst) {
    int i = blockIdx.x * blockDim.x + threadIdx.x;
    if (i < N_EDGES) {
        int d   = dst[i];
        int pos = atomicAdd(&g_cur[d], 1);
        g_col[pos] = src[i];
    }
}

// ---------------- layer 1 (K = 3, fp32 math, fp16 output) ----------------
__global__ void layer1_kernel(const float* __restrict__ x,
                              const float* __restrict__ Wl,
                              const float* __restrict__ Wr,
                              const float* __restrict__ b,
                              __half* __restrict__ hout) {
    __shared__ float aggx[64][4];
    __shared__ float xs[64][4];
    int tid  = threadIdx.x;
    int warp = tid >> 5, lane = tid & 31;
    int base = blockIdx.x * 64;

    for (int n = warp; n < 64; n += 4) {
        int node = base + n;
        if (node >= N_NODES) break;
        int s0 = g_off[node], e0 = g_off[node + 1];
        float a0 = 0.f, a1 = 0.f, a2 = 0.f;
        for (int idx = s0 + lane; idx < e0; idx += 32) {
            int j = g_col[idx];
            a0 += x[j * 3 + 0];
            a1 += x[j * 3 + 1];
            a2 += x[j * 3 + 2];
        }
        #pragma unroll
        for (int o = 16; o > 0; o >>= 1) {
            a0 += __shfl_xor_sync(0xffffffffu, a0, o);
            a1 += __shfl_xor_sync(0xffffffffu, a1, o);
            a2 += __shfl_xor_sync(0xffffffffu, a2, o);
        }
        if (lane == 0) {
            float di = g_deginv[node];
            aggx[n][0] = a0 * di; aggx[n][1] = a1 * di; aggx[n][2] = a2 * di;
            xs[n][0] = x[node * 3 + 0];
            xs[n][1] = x[node * 3 + 1];
            xs[n][2] = x[node * 3 + 2];
        }
    }
    __syncthreads();

    int t = tid;
    float wl0 = Wl[0 * CH + t], wl1 = Wl[1 * CH + t], wl2 = Wl[2 * CH + t];
    float wr0 = Wr[0 * CH + t], wr1 = Wr[1 * CH + t], wr2 = Wr[2 * CH + t];
    float bb  = b[t];
    for (int n = 0; n < 64; n++) {
        int node = base + n;
        if (node >= N_NODES) break;
        float acc = bb;
        acc += aggx[n][0] * wl0 + aggx[n][1] * wl1 + aggx[n][2] * wl2;
        acc += xs[n][0]   * wr0 + xs[n][1]   * wr1 + xs[n][2]   * wr2;
        hout[(size_t)node * CH + t] = __float2half(fmaxf(acc, 0.0f));
    }
}

// ---------------- layers 2/3: split-K two-pass fp16 TC GEMM, fp16 feature I/O ----------------
template <bool HALF_OUT>
__global__ void __launch_bounds__(256, 4)
layerTC_kernel(const __half* __restrict__ hin, void* __restrict__ hout_v,
               const __half* __restrict__ Wt, const float* __restrict__ bias) {
    __shared__ __align__(16) unsigned As[NPB * AS_H2];   // half2 elements

    int tid  = threadIdx.x;
    int warp = tid >> 5, lane = tid & 31;
    int base = blockIdx.x * NPB;

    int wm = warp >> 2;          // 0..1  -> M rows [wm*32, wm*32+32)
    int wn = warp & 3;           // 0..3  -> N cols [wn*32, wn*32+32)
    int gid = lane >> 2, tig = lane & 3;

    float acc[2][4][4];
    #pragma unroll
    for (int mt = 0; mt < 2; mt++)
        #pragma unroll
        for (int nt = 0; nt < 4; nt++)
            #pragma unroll
            for (int r = 0; r < 4; r++) acc[mt][nt][r] = 0.0f;

    const uint4* Wf = (const uint4*)Wt;

    #pragma unroll
    for (int pass = 0; pass < 2; pass++) {
        // ---- Phase A ----
        if (pass == 0) {
            for (int n = warp; n < NPB; n += 8) {
                int node = base + n;
                if (node >= N_NODES) break;      // tail block
                int s0 = g_off[node], e0 = g_off[node + 1];
                float4 A0 = make_float4(0.f, 0.f, 0.f, 0.f);
                float4 A1 = A0, A2 = A0, A3 = A0;
                int idx = s0;
                for (; idx + 4 <= e0; idx += 4) {
                    int j0 = g_col[idx + 0], j1 = g_col[idx + 1];
                    int j2 = g_col[idx + 2], j3 = g_col[idx + 3];
                    uint2 v0 = *(const uint2*)&hin[(size_t)j0 * CH + lane * 4];
                    uint2 v1 = *(const uint2*)&hin[(size_t)j1 * CH + lane * 4];
                    uint2 v2 = *(const uint2*)&hin[(size_t)j2 * CH + lane * 4];
                    uint2 v3 = *(const uint2*)&hin[(size_t)j3 * CH + lane * 4];
                    acc4_h2(A0, v0);
                    acc4_h2(A1, v1);
                    acc4_h2(A2, v2);
                    acc4_h2(A3, v3);
                }
                for (; idx < e0; idx++) {
                    int j = g_col[idx];
                    uint2 v = *(const uint2*)&hin[(size_t)j * CH + lane * 4];
                    acc4_h2(A0, v);
                }
                float di = g_deginv[node];
                float ax = ((A0.x + A1.x) + (A2.x + A3.x)) * di;
                float ay = ((A0.y + A1.y) + (A2.y + A3.y)) * di;
                float az = ((A0.z + A1.z) + (A2.z + A3.z)) * di;
                float aw = ((A0.w + A1.w) + (A2.w + A3.w)) * di;
                uint2 st;
                st.x = h2u(__floats2half2_rn(ax, ay));
                st.y = h2u(__floats2half2_rn(az, aw));
                *(uint2*)&As[n * AS_H2 + lane * 2] = st;
            }
        } else {
            for (int n = warp; n < NPB; n += 8) {
                int node = base + n;
                if (node >= N_NODES) break;
                uint2 own = *(const uint2*)&hin[(size_t)node * CH + lane * 4];
                *(uint2*)&As[n * AS_H2 + lane * 2] = own;
            }
        }
        __syncthreads();

        // ---- Phase B: accumulate (64x128) @ (128x128) via m16n8k16 fp16 ----
        #pragma unroll
        for (int kt = 0; kt < 8; kt++) {
            unsigned i0 = ((((unsigned)(wn * 2 + pass) * 8 + kt) * 2) * 32) + lane;
            uint4 q0 = Wf[i0];        // nt 0,1
            uint4 q1 = Wf[i0 + 32];   // nt 2,3
            unsigned bfr[4][2] = {
                { q0.x, q0.y }, { q0.z, q0.w },
                { q1.x, q1.y }, { q1.z, q1.w } };

            unsigned kc = kt * 8;     // half2 column base within row
            #pragma unroll
            for (int mt = 0; mt < 2; mt++) {
                unsigned r0 = (unsigned)(wm * 32 + mt * 16 + gid) * AS_H2 + kc + tig;
                unsigned a[4];
                a[0] = As[r0];
                a[1] = As[r0 + 8 * AS_H2];
                a[2] = As[r0 + 4];
                a[3] = As[r0 + 8 * AS_H2 + 4];
                #pragma unroll
                for (int nt = 0; nt < 4; nt++)
                    mma_f16(acc[mt][nt], a, bfr[nt]);
            }
        }
        __syncthreads();   // pass-1 Phase A must not overwrite before all reads done
    }

    // ---- epilogue: bias + relu + store ----
    #pragma unroll
    for (int nt = 0; nt < 4; nt++) {
        int col = wn * 32 + nt * 8 + tig * 2;
        float bb0 = bias[col], bb1 = bias[col + 1];
        #pragma unroll
        for (int mt = 0; mt < 2; mt++) {
            int row = base + wm * 32 + mt * 16 + gid;
            #pragma unroll
            for (int half_row = 0; half_row < 2; half_row++) {
                int r = row + half_row * 8;
                if (r >= N_NODES) continue;
                float vx = fmaxf(acc[mt][nt][half_row * 2 + 0] + bb0, 0.0f);
                float vy = fmaxf(acc[mt][nt][half_row * 2 + 1] + bb1, 0.0f);
                if (HALF_OUT) {
                    __half* ho = (__half*)hout_v;
                    __half2 hv = __floats2half2_rn(vx, vy);
                    *(__half2*)&ho[(size_t)r * CH + col] = hv;
                } else {
                    float* fo = (float*)hout_v;
                    float2 fv = make_float2(vx, vy);
                    *(float2*)&fo[(size_t)r * CH + col] = fv;
                }
            }
        }
    }
}

// ---------------- launch ----------------
extern "C" void kernel_launch(void* const* d_in, const int* in_sizes, int n_in,
                              void* d_out, int out_size) {
    const float* x   = (const float*)d_in[0];
    const int*   ei  = (const int*)d_in[1];      // [2, E]
    const float* W1l = (const float*)d_in[2];
    const float* W1r = (const float*)d_in[3];
    const float* b1  = (const float*)d_in[4];
    const float* W2l = (const float*)d_in[5];
    const float* W2r = (const float*)d_in[6];
    const float* b2  = (const float*)d_in[7];
    const float* W3l = (const float*)d_in[8];
    const float* W3r = (const float*)d_in[9];
    const float* b3  = (const float*)d_in[10];
    float* out = (float*)d_out;

    const int* src = ei;
    const int* dst = ei + N_EDGES;

    __half* h1; __half* h2; __half* Wt2; __half* Wt3; int* zp;
    cudaGetSymbolAddress((void**)&h1, g_h1);
    cudaGetSymbolAddress((void**)&h2, g_h2);
    cudaGetSymbolAddress((void**)&Wt2, g_Wt2);
    cudaGetSymbolAddress((void**)&Wt3, g_Wt3);
    cudaGetSymbolAddress((void**)&zp, g_zeroed);

    // one memset covers deg histogram + lookback flags
    cudaMemsetAsync(zp, 0, ZCOUNT * sizeof(int));
    histprep_kernel<<<PREP_BLOCKS + (N_EDGES + 255) / 256, 256>>>(dst, W2l, W2r, W3l, W3r);
    scanlb_kernel<<<NCHUNK, 1024>>>();
    fill_kernel<<<(N_EDGES + 255) / 256, 256>>>(src, dst);

    // layers
    layer1_kernel<<<(N_NODES + 63) / 64, 128>>>(x, W1l, W1r, b1, h1);
    layerTC_kernel<true><<<NBLK, 256>>>(h1, (void*)h2, Wt2, b2);
    layerTC_kernel<false><<<NBLK, 256>>>(h2, (void*)out, Wt3, b3);
}

// round 13
// speedup vs baseline: 1.6234x; 1.0670x over previous
#include <cuda_runtime.h>
#include <cuda_fp16.h>
#include <cstdint>

#define N_NODES 100000
#define N_EDGES 600000
#define CH 128
#define NPB 64            // nodes per block tile (tail block handles 32)
#define NBLK 1563         // ceil(100000/64)
#define NCHUNK 98         // ceil(100000/1024)
#define AS_H2 68          // half2 per row: 64 + 4 pad -> conflict-free fragment LDS
#define PREP_BLOCKS 16    // 4096 uint4 / 256
#define XPAD_BLOCKS 391   // ceil(100000/256)
#define ZCOUNT (N_NODES + 2 * NCHUNK)   // deg + lookback words, one memset

// ---------------- scratch (static device globals; no allocation) ----------------
__device__ __align__(16) int g_zeroed[ZCOUNT];   // [0,N): deg; [N,...): lookback u64
__device__ float  g_deginv[N_NODES];
__device__ int    g_off[N_NODES + 1];
__device__ int    g_cur[N_NODES];
__device__ int    g_col[N_EDGES];
__device__ __align__(16) float4 g_x4[N_NODES];   // x padded to 16B rows
__device__ __align__(16) __half g_h1[(size_t)N_NODES * CH];
__device__ __align__(16) __half g_h2[(size_t)N_NODES * CH];
// fp16 fragment-ordered weights: uint4 idx = ((((wn*2+pass)*8 + kt)*2 + g)*32 + lane)
__device__ __align__(16) __half g_Wt2[128 * 256];
__device__ __align__(16) __half g_Wt3[128 * 256];

// ---------------- helpers ----------------
__device__ __forceinline__ int warp_incl_scan(int v, int lane) {
    #pragma unroll
    for (int o = 1; o < 32; o <<= 1) {
        int t = __shfl_up_sync(0xffffffffu, v, o);
        if (lane >= o) v += t;
    }
    return v;
}
__device__ __forceinline__ void mma_f16(float* c, const unsigned* a, const unsigned* b) {
    asm volatile(
        "mma.sync.aligned.m16n8k16.row.col.f32.f16.f16.f32 "
        "{%0,%1,%2,%3}, {%4,%5,%6,%7}, {%8,%9}, {%0,%1,%2,%3};"
        : "+f"(c[0]), "+f"(c[1]), "+f"(c[2]), "+f"(c[3])
        : "r"(a[0]), "r"(a[1]), "r"(a[2]), "r"(a[3]), "r"(b[0]), "r"(b[1]));
}
__device__ __forceinline__ unsigned h2u(__half2 h) {
    return *reinterpret_cast<unsigned*>(&h);
}
__device__ __forceinline__ void acc4_h2(float4& A, uint2 v) {
    float2 lo = __half22float2(*reinterpret_cast<__half2*>(&v.x));
    float2 hi = __half22float2(*reinterpret_cast<__half2*>(&v.y));
    A.x += lo.x; A.y += lo.y; A.z += hi.x; A.w += hi.y;
}

// ---------------- fused prep (16) + x-pad (391) + degree histogram (rest) ----------------
__global__ void histprep_kernel(const int* __restrict__ dst,
                                const float* __restrict__ x,
                                const float* __restrict__ W2l, const float* __restrict__ W2r,
                                const float* __restrict__ W3l, const float* __restrict__ W3r) {
    if (blockIdx.x < PREP_BLOCKS) {
        int p = blockIdx.x * blockDim.x + threadIdx.x;   // 4096 uint4
        if (p >= 4096) return;
        int lane = p & 31;
        int g    = (p >> 5) & 1;
        int kt   = (p >> 6) & 7;
        int pass = (p >> 9) & 1;
        int wn   = (p >> 10) & 3;
        int gid = lane >> 2, tig = lane & 3;
        int k0 = kt * 16 + tig * 2;

        const float* Wa2 = pass ? W2r : W2l;
        const float* Wa3 = pass ? W3r : W3l;

        unsigned out2[4], out3[4];
        #pragma unroll
        for (int j = 0; j < 2; j++) {
            int n = wn * 32 + (g * 2 + j) * 8 + gid;
            out2[j * 2 + 0] = h2u(__floats2half2_rn(Wa2[(k0 + 0) * CH + n], Wa2[(k0 + 1) * CH + n]));
            out2[j * 2 + 1] = h2u(__floats2half2_rn(Wa2[(k0 + 8) * CH + n], Wa2[(k0 + 9) * CH + n]));
            out3[j * 2 + 0] = h2u(__floats2half2_rn(Wa3[(k0 + 0) * CH + n], Wa3[(k0 + 1) * CH + n]));
            out3[j * 2 + 1] = h2u(__floats2half2_rn(Wa3[(k0 + 8) * CH + n], Wa3[(k0 + 9) * CH + n]));
        }
        ((uint4*)g_Wt2)[p] = make_uint4(out2[0], out2[1], out2[2], out2[3]);
        ((uint4*)g_Wt3)[p] = make_uint4(out3[0], out3[1], out3[2], out3[3]);
    } else if (blockIdx.x < PREP_BLOCKS + XPAD_BLOCKS) {
        int i = (blockIdx.x - PREP_BLOCKS) * blockDim.x + threadIdx.x;
        if (i < N_NODES)
            g_x4[i] = make_float4(x[i * 3 + 0], x[i * 3 + 1], x[i * 3 + 2], 0.0f);
    } else {
        int i = (blockIdx.x - PREP_BLOCKS - XPAD_BLOCKS) * blockDim.x + threadIdx.x;
        if (i < N_EDGES) atomicAdd(&g_zeroed[dst[i]], 1);
    }
}

// ---------------- single-pass decoupled-lookback scan ----------------
__global__ void __launch_bounds__(1024, 1)
scanlb_kernel() {
    __shared__ int wsum[32];
    __shared__ int sh_excl;
    volatile unsigned long long* look =
        (volatile unsigned long long*)(g_zeroed + N_NODES);

    int b = blockIdx.x, tid = threadIdx.x;
    int wid = tid >> 5, lane = tid & 31;
    int i = b * 1024 + tid;
    int v = (i < N_NODES) ? g_zeroed[i] : 0;

    int incl = warp_incl_scan(v, lane);
    if (lane == 31) wsum[wid] = incl;
    __syncthreads();

    if (wid == 0) {
        int ws = wsum[lane];
        int wi = warp_incl_scan(ws, lane);
        wsum[lane] = wi - ws;                     // exclusive warp prefix
        int tot = __shfl_sync(0xffffffffu, wi, 31);

        if (lane == 0)
            look[b] = ((unsigned long long)(b == 0 ? 2u : 1u) << 32) | (unsigned)tot;

        int excl = 0;
        if (b > 0) {
            int win = b - 1;
            while (true) {
                int j = win - lane;
                unsigned long long s = 0;
                if (j >= 0) {
                    do { s = look[j]; } while ((unsigned)(s >> 32) == 0u);
                }
                unsigned flag = (j >= 0) ? (unsigned)(s >> 32) : 0u;
                int val = (int)(unsigned)s;
                unsigned mask = __ballot_sync(0xffffffffu, flag == 2u);
                int contrib;
                if (mask) {
                    int lz = __ffs(mask) - 1;
                    contrib = (lane <= lz && j >= 0) ? val : 0;
                } else {
                    contrib = (j >= 0) ? val : 0;
                }
                #pragma unroll
                for (int o = 16; o > 0; o >>= 1)
                    contrib += __shfl_xor_sync(0xffffffffu, contrib, o);
                excl += contrib;
                if (mask) break;
                win -= 32;
            }
            if (lane == 0)
                look[b] = (2ULL << 32) | (unsigned)(excl + tot);
        }
        if (lane == 0) sh_excl = excl;
    }
    __syncthreads();

    int inclusive = sh_excl + wsum[wid] + incl;
    if (i < N_NODES) {
        g_off[i + 1]  = inclusive;
        g_cur[i]      = inclusive - v;
        g_deginv[i]   = (v > 0) ? (1.0f / (float)v) : 0.0f;
        if (i == 0) g_off[0] = 0;
    }
}

__global__ void fill_kernel(const int* __restrict__ src, const int* __restrict__ dst) {
    int i = blockIdx.x * blockDim.x + threadIdx.x;
    if (i < N_EDGES) {
        int d   = dst[i];
        int pos = atomicAdd(&g_cur[d], 1);
        g_col[pos] = src[i];
    }
}

// ---------------- layer 1 (K = 3, fp32 math, fp16 output) ----------------
// 4 lanes per node (8 nodes/warp): float4 gather, 2-shuffle reduce.
__global__ void layer1_kernel(const float* __restrict__ Wl,
                              const float* __restrict__ Wr,
                              const float* __restrict__ b,
                              __half* __restrict__ hout) {
    __shared__ float aggx[64][4];
    __shared__ float xs[64][4];
    int tid  = threadIdx.x;
    int warp = tid >> 5, lane = tid & 31;
    int sub  = lane >> 2, sl = lane & 3;        // 8 sub-groups of 4 lanes
    int base = blockIdx.x * 64;

    #pragma unroll
    for (int pass = 0; pass < 2; pass++) {
        int n = pass * 32 + warp * 8 + sub;     // 0..63
        int node = base + n;
        if (node < N_NODES) {
            int s0 = g_off[node], e0 = g_off[node + 1];
            float a0 = 0.f, a1 = 0.f, a2 = 0.f;
            for (int idx = s0 + sl; idx < e0; idx += 4) {
                float4 v = g_x4[g_col[idx]];
                a0 += v.x; a1 += v.y; a2 += v.z;
            }
            #pragma unroll
            for (int o = 1; o < 4; o <<= 1) {
                a0 += __shfl_xor_sync(0xffffffffu, a0, o);
                a1 += __shfl_xor_sync(0xffffffffu, a1, o);
                a2 += __shfl_xor_sync(0xffffffffu, a2, o);
            }
            if (sl == 0) {
                float di = g_deginv[node];
                aggx[n][0] = a0 * di; aggx[n][1] = a1 * di; aggx[n][2] = a2 * di;
                float4 own = g_x4[node];
                xs[n][0] = own.x; xs[n][1] = own.y; xs[n][2] = own.z;
            }
        }
    }
    __syncthreads();

    int t = tid;
    float wl0 = Wl[0 * CH + t], wl1 = Wl[1 * CH + t], wl2 = Wl[2 * CH + t];
    float wr0 = Wr[0 * CH + t], wr1 = Wr[1 * CH + t], wr2 = Wr[2 * CH + t];
    float bb  = b[t];
    for (int n = 0; n < 64; n++) {
        int node = base + n;
        if (node >= N_NODES) break;
        float acc = bb;
        acc += aggx[n][0] * wl0 + aggx[n][1] * wl1 + aggx[n][2] * wl2;
        acc += xs[n][0]   * wr0 + xs[n][1]   * wr1 + xs[n][2]   * wr2;
        hout[(size_t)node * CH + t] = __float2half(fmaxf(acc, 0.0f));
    }
}

// ---------------- layers 2/3: split-K two-pass fp16 TC GEMM, fp16 feature I/O ----------------
template <bool HALF_OUT>
__global__ void __launch_bounds__(256, 4)
layerTC_kernel(const __half* __restrict__ hin, void* __restrict__ hout_v,
               const __half* __restrict__ Wt, const float* __restrict__ bias) {
    __shared__ __align__(16) unsigned As[NPB * AS_H2];   // half2 elements

    int tid  = threadIdx.x;
    int warp = tid >> 5, lane = tid & 31;
    int base = blockIdx.x * NPB;

    int wm = warp >> 2;          // 0..1  -> M rows [wm*32, wm*32+32)
    int wn = warp & 3;           // 0..3  -> N cols [wn*32, wn*32+32)
    int gid = lane >> 2, tig = lane & 3;

    float acc[2][4][4];
    #pragma unroll
    for (int mt = 0; mt < 2; mt++)
        #pragma unroll
        for (int nt = 0; nt < 4; nt++)
            #pragma unroll
            for (int r = 0; r < 4; r++) acc[mt][nt][r] = 0.0f;

    const uint4* Wf = (const uint4*)Wt;

    #pragma unroll
    for (int pass = 0; pass < 2; pass++) {
        // ---- Phase A ----
        if (pass == 0) {
            for (int n = warp; n < NPB; n += 8) {
                int node = base + n;
                if (node >= N_NODES) break;      // tail block
                int s0 = g_off[node], e0 = g_off[node + 1];
                float4 A0 = make_float4(0.f, 0.f, 0.f, 0.f);
                float4 A1 = A0, A2 = A0, A3 = A0;
                int idx = s0;
                for (; idx + 4 <= e0; idx += 4) {
                    int j0 = g_col[idx + 0], j1 = g_col[idx + 1];
                    int j2 = g_col[idx + 2], j3 = g_col[idx + 3];
                    uint2 v0 = *(const uint2*)&hin[(size_t)j0 * CH + lane * 4];
                    uint2 v1 = *(const uint2*)&hin[(size_t)j1 * CH + lane * 4];
                    uint2 v2 = *(const uint2*)&hin[(size_t)j2 * CH + lane * 4];
                    uint2 v3 = *(const uint2*)&hin[(size_t)j3 * CH + lane * 4];
                    acc4_h2(A0, v0);
                    acc4_h2(A1, v1);
                    acc4_h2(A2, v2);
                    acc4_h2(A3, v3);
                }
                for (; idx < e0; idx++) {
                    int j = g_col[idx];
                    uint2 v = *(const uint2*)&hin[(size_t)j * CH + lane * 4];
                    acc4_h2(A0, v);
                }
                float di = g_deginv[node];
                float ax = ((A0.x + A1.x) + (A2.x + A3.x)) * di;
                float ay = ((A0.y + A1.y) + (A2.y + A3.y)) * di;
                float az = ((A0.z + A1.z) + (A2.z + A3.z)) * di;
                float aw = ((A0.w + A1.w) + (A2.w + A3.w)) * di;
                uint2 st;
                st.x = h2u(__floats2half2_rn(ax, ay));
                st.y = h2u(__floats2half2_rn(az, aw));
                *(uint2*)&As[n * AS_H2 + lane * 2] = st;
            }
        } else {
            for (int n = warp; n < NPB; n += 8) {
                int node = base + n;
                if (node >= N_NODES) break;
                uint2 own = *(const uint2*)&hin[(size_t)node * CH + lane * 4];
                *(uint2*)&As[n * AS_H2 + lane * 2] = own;
            }
        }
        __syncthreads();

        // ---- Phase B: accumulate (64x128) @ (128x128) via m16n8k16 fp16 ----
        #pragma unroll
        for (int kt = 0; kt < 8; kt++) {
            unsigned i0 = ((((unsigned)(wn * 2 + pass) * 8 + kt) * 2) * 32) + lane;
            uint4 q0 = Wf[i0];        // nt 0,1
            uint4 q1 = Wf[i0 + 32];   // nt 2,3
            unsigned bfr[4][2] = {
                { q0.x, q0.y }, { q0.z, q0.w },
                { q1.x, q1.y }, { q1.z, q1.w } };

            unsigned kc = kt * 8;     // half2 column base within row
            #pragma unroll
            for (int mt = 0; mt < 2; mt++) {
                unsigned r0 = (unsigned)(wm * 32 + mt * 16 + gid) * AS_H2 + kc + tig;
                unsigned a[4];
                a[0] = As[r0];
                a[1] = As[r0 + 8 * AS_H2];
                a[2] = As[r0 + 4];
                a[3] = As[r0 + 8 * AS_H2 + 4];
                #pragma unroll
                for (int nt = 0; nt < 4; nt++)
                    mma_f16(acc[mt][nt], a, bfr[nt]);
            }
        }
        __syncthreads();   // pass-1 Phase A must not overwrite before all reads done
    }

    // ---- epilogue: bias + relu + store ----
    #pragma unroll
    for (int nt = 0; nt < 4; nt++) {
        int col = wn * 32 + nt * 8 + tig * 2;
        float bb0 = bias[col], bb1 = bias[col + 1];
        #pragma unroll
        for (int mt = 0; mt < 2; mt++) {
            int row = base + wm * 32 + mt * 16 + gid;
            #pragma unroll
            for (int half_row = 0; half_row < 2; half_row++) {
                int r = row + half_row * 8;
                if (r >= N_NODES) continue;
                float vx = fmaxf(acc[mt][nt][half_row * 2 + 0] + bb0, 0.0f);
                float vy = fmaxf(acc[mt][nt][half_row * 2 + 1] + bb1, 0.0f);
                if (HALF_OUT) {
                    __half* ho = (__half*)hout_v;
                    __half2 hv = __floats2half2_rn(vx, vy);
                    *(__half2*)&ho[(size_t)r * CH + col] = hv;
                } else {
                    float* fo = (float*)hout_v;
                    float2 fv = make_float2(vx, vy);
                    *(float2*)&fo[(size_t)r * CH + col] = fv;
                }
            }
        }
    }
}

// ---------------- launch ----------------
extern "C" void kernel_launch(void* const* d_in, const int* in_sizes, int n_in,
                              void* d_out, int out_size) {
    const float* x   = (const float*)d_in[0];
    const int*   ei  = (const int*)d_in[1];      // [2, E]
    const float* W1l = (const float*)d_in[2];
    const float* W1r = (const float*)d_in[3];
    const float* b1  = (const float*)d_in[4];
    const float* W2l = (const float*)d_in[5];
    const float* W2r = (const float*)d_in[6];
    const float* b2  = (const float*)d_in[7];
    const float* W3l = (const float*)d_in[8];
    const float* W3r = (const float*)d_in[9];
    const float* b3  = (const float*)d_in[10];
    float* out = (float*)d_out;

    const int* src = ei;
    const int* dst = ei + N_EDGES;

    __half* h1; __half* h2; __half* Wt2; __half* Wt3; int* zp;
    cudaGetSymbolAddress((void**)&h1, g_h1);
    cudaGetSymbolAddress((void**)&h2, g_h2);
    cudaGetSymbolAddress((void**)&Wt2, g_Wt2);
    cudaGetSymbolAddress((void**)&Wt3, g_Wt3);
    cudaGetSymbolAddress((void**)&zp, g_zeroed);

    // one memset covers deg histogram + lookback flags
    cudaMemsetAsync(zp, 0, ZCOUNT * sizeof(int));
    histprep_kernel<<<PREP_BLOCKS + XPAD_BLOCKS + (N_EDGES + 255) / 256, 256>>>(
        dst, x, W2l, W2r, W3l, W3r);
    scanlb_kernel<<<NCHUNK, 1024>>>();
    fill_kernel<<<(N_EDGES + 255) / 256, 256>>>(src, dst);

    // layers
    layer1_kernel<<<(N_NODES + 63) / 64, 128>>>(W1l, W1r, b1, h1);
    layerTC_kernel<true><<<NBLK, 256>>>(h1, (void*)h2, Wt2, b2);
    layerTC_kernel<false><<<NBLK, 256>>>(h2, (void*)out, Wt3, b3);
}

// round 14
// speedup vs baseline: 1.7123x; 1.0548x over previous
#include <cuda_runtime.h>
#include <cuda_fp16.h>
#include <cstdint>

#define N_NODES 100000
#define N_EDGES 600000
#define CH 128
#define NPB 64            // nodes per block tile (tail block handles 32)
#define NBLK 1563         // ceil(100000/64)
#define NCHUNK 98         // ceil(100000/1024)
#define AS_H2 68          // half2 per row: 64 + 4 pad -> conflict-free fragment LDS
#define PREP_BLOCKS 16    // 4096 uint4 / 256
#define XPAD_BLOCKS 391   // ceil(100000/256)
#define ZCOUNT (N_NODES + 2 * NCHUNK)   // deg + lookback words, one memset

// ---------------- scratch (static device globals; no allocation) ----------------
__device__ __align__(16) int g_zeroed[ZCOUNT];   // [0,N): deg; [N,...): lookback u64
__device__ float  g_deginv[N_NODES];
__device__ int    g_off[N_NODES + 1];
__device__ int    g_cur[N_NODES];
__device__ int    g_col[N_EDGES];
__device__ __align__(16) float4 g_x4[N_NODES];   // x padded to 16B rows
__device__ __align__(16) __half g_h1[(size_t)N_NODES * CH];
__device__ __align__(16) __half g_h2[(size_t)N_NODES * CH];
// fp16 fragment-ordered weights: uint4 idx = ((((wn*2+pass)*8 + kt)*2 + g)*32 + lane)
__device__ __align__(16) __half g_Wt2[128 * 256];
__device__ __align__(16) __half g_Wt3[128 * 256];

// ---------------- helpers ----------------
__device__ __forceinline__ int warp_incl_scan(int v, int lane) {
    #pragma unroll
    for (int o = 1; o < 32; o <<= 1) {
        int t = __shfl_up_sync(0xffffffffu, v, o);
        if (lane >= o) v += t;
    }
    return v;
}
__device__ __forceinline__ void mma_f16(float* c, const unsigned* a, const unsigned* b) {
    asm volatile(
        "mma.sync.aligned.m16n8k16.row.col.f32.f16.f16.f32 "
        "{%0,%1,%2,%3}, {%4,%5,%6,%7}, {%8,%9}, {%0,%1,%2,%3};"
        : "+f"(c[0]), "+f"(c[1]), "+f"(c[2]), "+f"(c[3])
        : "r"(a[0]), "r"(a[1]), "r"(a[2]), "r"(a[3]), "r"(b[0]), "r"(b[1]));
}
__device__ __forceinline__ unsigned h2u(__half2 h) {
    return *reinterpret_cast<unsigned*>(&h);
}
__device__ __forceinline__ void acc4_h2(float4& A, uint2 v) {
    float2 lo = __half22float2(*reinterpret_cast<__half2*>(&v.x));
    float2 hi = __half22float2(*reinterpret_cast<__half2*>(&v.y));
    A.x += lo.x; A.y += lo.y; A.z += hi.x; A.w += hi.y;
}

// ---------------- fused prep (16) + x-pad (391) + degree histogram (rest) ----------------
__global__ void histprep_kernel(const int* __restrict__ dst,
                                const float* __restrict__ x,
                                const float* __restrict__ W2l, const float* __restrict__ W2r,
                                const float* __restrict__ W3l, const float* __restrict__ W3r) {
    if (blockIdx.x < PREP_BLOCKS) {
        int p = blockIdx.x * blockDim.x + threadIdx.x;   // 4096 uint4
        if (p >= 4096) return;
        int lane = p & 31;
        int g    = (p >> 5) & 1;
        int kt   = (p >> 6) & 7;
        int pass = (p >> 9) & 1;
        int wn   = (p >> 10) & 3;
        int gid = lane >> 2, tig = lane & 3;
        int k0 = kt * 16 + tig * 2;

        const float* Wa2 = pass ? W2r : W2l;
        const float* Wa3 = pass ? W3r : W3l;

        unsigned out2[4], out3[4];
        #pragma unroll
        for (int j = 0; j < 2; j++) {
            int n = wn * 32 + (g * 2 + j) * 8 + gid;
            out2[j * 2 + 0] = h2u(__floats2half2_rn(Wa2[(k0 + 0) * CH + n], Wa2[(k0 + 1) * CH + n]));
            out2[j * 2 + 1] = h2u(__floats2half2_rn(Wa2[(k0 + 8) * CH + n], Wa2[(k0 + 9) * CH + n]));
            out3[j * 2 + 0] = h2u(__floats2half2_rn(Wa3[(k0 + 0) * CH + n], Wa3[(k0 + 1) * CH + n]));
            out3[j * 2 + 1] = h2u(__floats2half2_rn(Wa3[(k0 + 8) * CH + n], Wa3[(k0 + 9) * CH + n]));
        }
        ((uint4*)g_Wt2)[p] = make_uint4(out2[0], out2[1], out2[2], out2[3]);
        ((uint4*)g_Wt3)[p] = make_uint4(out3[0], out3[1], out3[2], out3[3]);
    } else if (blockIdx.x < PREP_BLOCKS + XPAD_BLOCKS) {
        int i = (blockIdx.x - PREP_BLOCKS) * blockDim.x + threadIdx.x;
        if (i < N_NODES)
            g_x4[i] = make_float4(x[i * 3 + 0], x[i * 3 + 1], x[i * 3 + 2], 0.0f);
    } else {
        int i = (blockIdx.x - PREP_BLOCKS - XPAD_BLOCKS) * blockDim.x + threadIdx.x;
        if (i < N_EDGES) atomicAdd(&g_zeroed[dst[i]], 1);
    }
}

// ---------------- single-pass decoupled-lookback scan ----------------
__global__ void __launch_bounds__(1024, 1)
scanlb_kernel() {
    __shared__ int wsum[32];
    __shared__ int sh_excl;
    volatile unsigned long long* look =
        (volatile unsigned long long*)(g_zeroed + N_NODES);

    int b = blockIdx.x, tid = threadIdx.x;
    int wid = tid >> 5, lane = tid & 31;
    int i = b * 1024 + tid;
    int v = (i < N_NODES) ? g_zeroed[i] : 0;

    int incl = warp_incl_scan(v, lane);
    if (lane == 31) wsum[wid] = incl;
    __syncthreads();

    if (wid == 0) {
        int ws = wsum[lane];
        int wi = warp_incl_scan(ws, lane);
        wsum[lane] = wi - ws;                     // exclusive warp prefix
        int tot = __shfl_sync(0xffffffffu, wi, 31);

        if (lane == 0)
            look[b] = ((unsigned long long)(b == 0 ? 2u : 1u) << 32) | (unsigned)tot;

        int excl = 0;
        if (b > 0) {
            int win = b - 1;
            while (true) {
                int j = win - lane;
                unsigned long long s = 0;
                if (j >= 0) {
                    do { s = look[j]; } while ((unsigned)(s >> 32) == 0u);
                }
                unsigned flag = (j >= 0) ? (unsigned)(s >> 32) : 0u;
                int val = (int)(unsigned)s;
                unsigned mask = __ballot_sync(0xffffffffu, flag == 2u);
                int contrib;
                if (mask) {
                    int lz = __ffs(mask) - 1;
                    contrib = (lane <= lz && j >= 0) ? val : 0;
                } else {
                    contrib = (j >= 0) ? val : 0;
                }
                #pragma unroll
                for (int o = 16; o > 0; o >>= 1)
                    contrib += __shfl_xor_sync(0xffffffffu, contrib, o);
                excl += contrib;
                if (mask) break;
                win -= 32;
            }
            if (lane == 0)
                look[b] = (2ULL << 32) | (unsigned)(excl + tot);
        }
        if (lane == 0) sh_excl = excl;
    }
    __syncthreads();

    int inclusive = sh_excl + wsum[wid] + incl;
    if (i < N_NODES) {
        g_off[i + 1]  = inclusive;
        g_cur[i]      = inclusive - v;
        g_deginv[i]   = (v > 0) ? (1.0f / (float)v) : 0.0f;
        if (i == 0) g_off[0] = 0;
    }
}

__global__ void fill_kernel(const int* __restrict__ src, const int* __restrict__ dst) {
    int i = blockIdx.x * blockDim.x + threadIdx.x;
    if (i < N_EDGES) {
        int d   = dst[i];
        int pos = atomicAdd(&g_cur[d], 1);
        g_col[pos] = src[i];
    }
}

// ---------------- layer 1 (K = 3, fp32 math, fp16 output) ----------------
// 4 lanes per node (8 nodes/warp). Gather: 2 clamped loads in flight per wave,
// predicated accumulate -> deg<=8 resolves in one latency wave.
__global__ void layer1_kernel(const float* __restrict__ Wl,
                              const float* __restrict__ Wr,
                              const float* __restrict__ b,
                              __half* __restrict__ hout) {
    __shared__ __align__(16) float aggx[64][4];
    __shared__ __align__(16) float xs[64][4];
    int tid  = threadIdx.x;
    int warp = tid >> 5, lane = tid & 31;
    int sub  = lane >> 2, sl = lane & 3;        // 8 sub-groups of 4 lanes
    int base = blockIdx.x * 64;

    #pragma unroll
    for (int pass = 0; pass < 2; pass++) {
        int n = pass * 32 + warp * 8 + sub;     // 0..63
        int node = base + n;
        if (node < N_NODES) {
            int s0 = g_off[node], e0 = g_off[node + 1];
            int safe = min(s0, N_EDGES - 1);
            float a0 = 0.f, a1 = 0.f, a2 = 0.f;
            float b0 = 0.f, b1 = 0.f, b2 = 0.f;
            for (int w = s0; w < e0; w += 8) {
                int i0 = w + sl, i1 = w + sl + 4;
                bool p0 = i0 < e0, p1 = i1 < e0;
                int j0 = g_col[p0 ? i0 : safe];
                int j1 = g_col[p1 ? i1 : safe];
                float4 v0 = g_x4[j0];
                float4 v1 = g_x4[j1];
                if (p0) { a0 += v0.x; a1 += v0.y; a2 += v0.z; }
                if (p1) { b0 += v1.x; b1 += v1.y; b2 += v1.z; }
            }
            a0 += b0; a1 += b1; a2 += b2;
            #pragma unroll
            for (int o = 1; o < 4; o <<= 1) {
                a0 += __shfl_xor_sync(0xffffffffu, a0, o);
                a1 += __shfl_xor_sync(0xffffffffu, a1, o);
                a2 += __shfl_xor_sync(0xffffffffu, a2, o);
            }
            if (sl == 0) {
                float di = g_deginv[node];
                float4 agg = make_float4(a0 * di, a1 * di, a2 * di, 0.0f);
                *(float4*)&aggx[n][0] = agg;
                *(float4*)&xs[n][0] = g_x4[node];
            }
        }
    }
    __syncthreads();

    int t = tid;
    float wl0 = Wl[0 * CH + t], wl1 = Wl[1 * CH + t], wl2 = Wl[2 * CH + t];
    float wr0 = Wr[0 * CH + t], wr1 = Wr[1 * CH + t], wr2 = Wr[2 * CH + t];
    float bb  = b[t];
    for (int n = 0; n < 64; n++) {
        int node = base + n;
        if (node >= N_NODES) break;
        float4 ag = *(const float4*)&aggx[n][0];
        float4 ow = *(const float4*)&xs[n][0];
        float acc = bb;
        acc += ag.x * wl0 + ag.y * wl1 + ag.z * wl2;
        acc += ow.x * wr0 + ow.y * wr1 + ow.z * wr2;
        hout[(size_t)node * CH + t] = __float2half(fmaxf(acc, 0.0f));
    }
}

// ---------------- layers 2/3: split-K two-pass fp16 TC GEMM, fp16 feature I/O ----------------
// Phase A processes node PAIRS (n, n+8) with clamped/predicated batches of 4 each
// -> 8 gather loads in flight per wave, no serial remainder.
template <bool HALF_OUT>
__global__ void __launch_bounds__(256, 4)
layerTC_kernel(const __half* __restrict__ hin, void* __restrict__ hout_v,
               const __half* __restrict__ Wt, const float* __restrict__ bias) {
    __shared__ __align__(16) unsigned As[NPB * AS_H2];   // half2 elements

    int tid  = threadIdx.x;
    int warp = tid >> 5, lane = tid & 31;
    int base = blockIdx.x * NPB;

    int wm = warp >> 2;          // 0..1  -> M rows [wm*32, wm*32+32)
    int wn = warp & 3;           // 0..3  -> N cols [wn*32, wn*32+32)
    int gid = lane >> 2, tig = lane & 3;

    float acc[2][4][4];
    #pragma unroll
    for (int mt = 0; mt < 2; mt++)
        #pragma unroll
        for (int nt = 0; nt < 4; nt++)
            #pragma unroll
            for (int r = 0; r < 4; r++) acc[mt][nt][r] = 0.0f;

    const uint4* Wf = (const uint4*)Wt;

    #pragma unroll
    for (int pass = 0; pass < 2; pass++) {
        // ---- Phase A ----
        if (pass == 0) {
            #pragma unroll
            for (int q = 0; q < 4; q++) {
                int nA = warp + q * 16;           // rows warp, warp+16, warp+32, warp+48
                int nB = nA + 8;
                int nodeA = base + nA, nodeB = base + nB;
                bool okA = nodeA < N_NODES, okB = nodeB < N_NODES;
                int sA = okA ? g_off[nodeA] : 0, eA = okA ? g_off[nodeA + 1] : 0;
                int sB = okB ? g_off[nodeB] : 0, eB = okB ? g_off[nodeB + 1] : 0;
                int safeA = min(sA, N_EDGES - 1);
                int safeB = min(sB, N_EDGES - 1);
                int degA = eA - sA, degB = eB - sB;
                int maxd = max(degA, degB);

                float4 A0 = make_float4(0.f, 0.f, 0.f, 0.f);
                float4 A1 = A0, B0 = A0, B1 = A0;

                for (int w = 0; w < maxd; w += 4) {
                    int ja[4], jb[4];
                    bool pa[4], pb[4];
                    #pragma unroll
                    for (int j = 0; j < 4; j++) {
                        int ia = sA + w + j, ib = sB + w + j;
                        pa[j] = ia < eA;  pb[j] = ib < eB;
                        ja[j] = g_col[pa[j] ? ia : safeA];
                        jb[j] = g_col[pb[j] ? ib : safeB];
                    }
                    uint2 va0 = *(const uint2*)&hin[(size_t)ja[0] * CH + lane * 4];
                    uint2 va1 = *(const uint2*)&hin[(size_t)ja[1] * CH + lane * 4];
                    uint2 va2 = *(const uint2*)&hin[(size_t)ja[2] * CH + lane * 4];
                    uint2 va3 = *(const uint2*)&hin[(size_t)ja[3] * CH + lane * 4];
                    uint2 vb0 = *(const uint2*)&hin[(size_t)jb[0] * CH + lane * 4];
                    uint2 vb1 = *(const uint2*)&hin[(size_t)jb[1] * CH + lane * 4];
                    uint2 vb2 = *(const uint2*)&hin[(size_t)jb[2] * CH + lane * 4];
                    uint2 vb3 = *(const uint2*)&hin[(size_t)jb[3] * CH + lane * 4];
                    if (pa[0]) acc4_h2(A0, va0);
                    if (pa[1]) acc4_h2(A1, va1);
                    if (pa[2]) acc4_h2(A0, va2);
                    if (pa[3]) acc4_h2(A1, va3);
                    if (pb[0]) acc4_h2(B0, vb0);
                    if (pb[1]) acc4_h2(B1, vb1);
                    if (pb[2]) acc4_h2(B0, vb2);
                    if (pb[3]) acc4_h2(B1, vb3);
                }

                if (okA) {
                    float di = g_deginv[nodeA];
                    uint2 st;
                    st.x = h2u(__floats2half2_rn((A0.x + A1.x) * di, (A0.y + A1.y) * di));
                    st.y = h2u(__floats2half2_rn((A0.z + A1.z) * di, (A0.w + A1.w) * di));
                    *(uint2*)&As[nA * AS_H2 + lane * 2] = st;
                }
                if (okB) {
                    float di = g_deginv[nodeB];
                    uint2 st;
                    st.x = h2u(__floats2half2_rn((B0.x + B1.x) * di, (B0.y + B1.y) * di));
                    st.y = h2u(__floats2half2_rn((B0.z + B1.z) * di, (B0.w + B1.w) * di));
                    *(uint2*)&As[nB * AS_H2 + lane * 2] = st;
                }
            }
        } else {
            for (int n = warp; n < NPB; n += 8) {
                int node = base + n;
                if (node >= N_NODES) break;
                uint2 own = *(const uint2*)&hin[(size_t)node * CH + lane * 4];
                *(uint2*)&As[n * AS_H2 + lane * 2] = own;
            }
        }
        __syncthreads();

        // ---- Phase B: accumulate (64x128) @ (128x128) via m16n8k16 fp16 ----
        #pragma unroll
        for (int kt = 0; kt < 8; kt++) {
            unsigned i0 = ((((unsigned)(wn * 2 + pass) * 8 + kt) * 2) * 32) + lane;
            uint4 q0 = Wf[i0];        // nt 0,1
            uint4 q1 = Wf[i0 + 32];   // nt 2,3
            unsigned bfr[4][2] = {
                { q0.x, q0.y }, { q0.z, q0.w },
                { q1.x, q1.y }, { q1.z, q1.w } };

            unsigned kc = kt * 8;     // half2 column base within row
            #pragma unroll
            for (int mt = 0; mt < 2; mt++) {
                unsigned r0 = (unsigned)(wm * 32 + mt * 16 + gid) * AS_H2 + kc + tig;
                unsigned a[4];
                a[0] = As[r0];
                a[1] = As[r0 + 8 * AS_H2];
                a[2] = As[r0 + 4];
                a[3] = As[r0 + 8 * AS_H2 + 4];
                #pragma unroll
                for (int nt = 0; nt < 4; nt++)
                    mma_f16(acc[mt][nt], a, bfr[nt]);
            }
        }
        __syncthreads();   // pass-1 Phase A must not overwrite before all reads done
    }

    // ---- epilogue: bias + relu + store ----
    #pragma unroll
    for (int nt = 0; nt < 4; nt++) {
        int col = wn * 32 + nt * 8 + tig * 2;
        float bb0 = bias[col], bb1 = bias[col + 1];
        #pragma unroll
        for (int mt = 0; mt < 2; mt++) {
            int row = base + wm * 32 + mt * 16 + gid;
            #pragma unroll
            for (int half_row = 0; half_row < 2; half_row++) {
                int r = row + half_row * 8;
                if (r >= N_NODES) continue;
                float vx = fmaxf(acc[mt][nt][half_row * 2 + 0] + bb0, 0.0f);
                float vy = fmaxf(acc[mt][nt][half_row * 2 + 1] + bb1, 0.0f);
                if (HALF_OUT) {
                    __half* ho = (__half*)hout_v;
                    __half2 hv = __floats2half2_rn(vx, vy);
                    *(__half2*)&ho[(size_t)r * CH + col] = hv;
                } else {
                    float* fo = (float*)hout_v;
                    float2 fv = make_float2(vx, vy);
                    *(float2*)&fo[(size_t)r * CH + col] = fv;
                }
            }
        }
    }
}

// ---------------- launch ----------------
extern "C" void kernel_launch(void* const* d_in, const int* in_sizes, int n_in,
                              void* d_out, int out_size) {
    const float* x   = (const float*)d_in[0];
    const int*   ei  = (const int*)d_in[1];      // [2, E]
    const float* W1l = (const float*)d_in[2];
    const float* W1r = (const float*)d_in[3];
    const float* b1  = (const float*)d_in[4];
    const float* W2l = (const float*)d_in[5];
    const float* W2r = (const float*)d_in[6];
    const float* b2  = (const float*)d_in[7];
    const float* W3l = (const float*)d_in[8];
    const float* W3r = (const float*)d_in[9];
    const float* b3  = (const float*)d_in[10];
    float* out = (float*)d_out;

    const int* src = ei;
    const int* dst = ei + N_EDGES;

    __half* h1; __half* h2; __half* Wt2; __half* Wt3; int* zp;
    cudaGetSymbolAddress((void**)&h1, g_h1);
    cudaGetSymbolAddress((void**)&h2, g_h2);
    cudaGetSymbolAddress((void**)&Wt2, g_Wt2);
    cudaGetSymbolAddress((void**)&Wt3, g_Wt3);
    cudaGetSymbolAddress((void**)&zp, g_zeroed);

    // one memset covers deg histogram + lookback flags
    cudaMemsetAsync(zp, 0, ZCOUNT * sizeof(int));
    histprep_kernel<<<PREP_BLOCKS + XPAD_BLOCKS + (N_EDGES + 255) / 256, 256>>>(
        dst, x, W2l, W2r, W3l, W3r);
    scanlb_kernel<<<NCHUNK, 1024>>>();
    fill_kernel<<<(N_EDGES + 255) / 256, 256>>>(src, dst);

    // layers
    layer1_kernel<<<(N_NODES + 63) / 64, 128>>>(W1l, W1r, b1, h1);
    layerTC_kernel<true><<<NBLK, 256>>>(h1, (void*)h2, Wt2, b2);
    layerTC_kernel<false><<<NBLK, 256>>>(h2, (void*)out, Wt3, b3);
}

// round 15
// speedup vs baseline: 1.7395x; 1.0159x over previous
#include <cuda_runtime.h>
#include <cuda_fp16.h>
#include <cstdint>

#define N_NODES 100000
#define N_EDGES 600000
#define CH 128
#define NPB 64            // nodes per block tile (tail block handles 32)
#define NBLK 1563         // ceil(100000/64)
#define NCHUNK 98         // ceil(100000/1024)
#define AS_H2 68          // half2 per row: 64 + 4 pad -> conflict-free fragment LDS
#define PREP_BLOCKS 16    // 4096 uint4 / 256
#define XPAD_BLOCKS 391   // ceil(100000/256)
#define ZCOUNT (N_NODES + 2 * NCHUNK)   // deg + lookback words, one memset

// ---------------- scratch (static device globals; no allocation) ----------------
__device__ __align__(16) int g_zeroed[ZCOUNT];   // [0,N): deg; [N,...): lookback u64
__device__ float  g_deginv[N_NODES];
__device__ int    g_off[N_NODES + 1];
__device__ int    g_cur[N_NODES];
__device__ int    g_col[N_EDGES];
__device__ __align__(16) float4 g_x4[N_NODES];   // x padded to 16B rows
__device__ __align__(16) __half g_h1[(size_t)N_NODES * CH];
__device__ __align__(16) __half g_h2[(size_t)N_NODES * CH];
// fp16 fragment-ordered weights: uint4 idx = ((((wn*2+pass)*8 + kt)*2 + g)*32 + lane)
__device__ __align__(16) __half g_Wt2[128 * 256];
__device__ __align__(16) __half g_Wt3[128 * 256];

// ---------------- helpers ----------------
__device__ __forceinline__ int warp_incl_scan(int v, int lane) {
    #pragma unroll
    for (int o = 1; o < 32; o <<= 1) {
        int t = __shfl_up_sync(0xffffffffu, v, o);
        if (lane >= o) v += t;
    }
    return v;
}
__device__ __forceinline__ void mma_f16(float* c, const unsigned* a, const unsigned* b) {
    asm volatile(
        "mma.sync.aligned.m16n8k16.row.col.f32.f16.f16.f32 "
        "{%0,%1,%2,%3}, {%4,%5,%6,%7}, {%8,%9}, {%0,%1,%2,%3};"
        : "+f"(c[0]), "+f"(c[1]), "+f"(c[2]), "+f"(c[3])
        : "r"(a[0]), "r"(a[1]), "r"(a[2]), "r"(a[3]), "r"(b[0]), "r"(b[1]));
}
__device__ __forceinline__ unsigned h2u(__half2 h) {
    return *reinterpret_cast<unsigned*>(&h);
}
__device__ __forceinline__ void acc4_h2(float4& A, uint2 v) {
    float2 lo = __half22float2(*reinterpret_cast<__half2*>(&v.x));
    float2 hi = __half22float2(*reinterpret_cast<__half2*>(&v.y));
    A.x += lo.x; A.y += lo.y; A.z += hi.x; A.w += hi.y;
}

// ---------------- fused prep (16) + x-pad (391) + degree histogram (rest) ----------------
__global__ void histprep_kernel(const int* __restrict__ dst,
                                const float* __restrict__ x,
                                const float* __restrict__ W2l, const float* __restrict__ W2r,
                                const float* __restrict__ W3l, const float* __restrict__ W3r) {
    if (blockIdx.x < PREP_BLOCKS) {
        int p = blockIdx.x * blockDim.x + threadIdx.x;   // 4096 uint4
        if (p >= 4096) return;
        int lane = p & 31;
        int g    = (p >> 5) & 1;
        int kt   = (p >> 6) & 7;
        int pass = (p >> 9) & 1;
        int wn   = (p >> 10) & 3;
        int gid = lane >> 2, tig = lane & 3;
        int k0 = kt * 16 + tig * 2;

        const float* Wa2 = pass ? W2r : W2l;
        const float* Wa3 = pass ? W3r : W3l;

        unsigned out2[4], out3[4];
        #pragma unroll
        for (int j = 0; j < 2; j++) {
            int n = wn * 32 + (g * 2 + j) * 8 + gid;
            out2[j * 2 + 0] = h2u(__floats2half2_rn(Wa2[(k0 + 0) * CH + n], Wa2[(k0 + 1) * CH + n]));
            out2[j * 2 + 1] = h2u(__floats2half2_rn(Wa2[(k0 + 8) * CH + n], Wa2[(k0 + 9) * CH + n]));
            out3[j * 2 + 0] = h2u(__floats2half2_rn(Wa3[(k0 + 0) * CH + n], Wa3[(k0 + 1) * CH + n]));
            out3[j * 2 + 1] = h2u(__floats2half2_rn(Wa3[(k0 + 8) * CH + n], Wa3[(k0 + 9) * CH + n]));
        }
        ((uint4*)g_Wt2)[p] = make_uint4(out2[0], out2[1], out2[2], out2[3]);
        ((uint4*)g_Wt3)[p] = make_uint4(out3[0], out3[1], out3[2], out3[3]);
    } else if (blockIdx.x < PREP_BLOCKS + XPAD_BLOCKS) {
        int i = (blockIdx.x - PREP_BLOCKS) * blockDim.x + threadIdx.x;
        if (i < N_NODES)
            g_x4[i] = make_float4(x[i * 3 + 0], x[i * 3 + 1], x[i * 3 + 2], 0.0f);
    } else {
        int i = (blockIdx.x - PREP_BLOCKS - XPAD_BLOCKS) * blockDim.x + threadIdx.x;
        if (i < N_EDGES) atomicAdd(&g_zeroed[dst[i]], 1);
    }
}

// ---------------- single-pass decoupled-lookback scan ----------------
__global__ void __launch_bounds__(1024, 1)
scanlb_kernel() {
    __shared__ int wsum[32];
    __shared__ int sh_excl;
    volatile unsigned long long* look =
        (volatile unsigned long long*)(g_zeroed + N_NODES);

    int b = blockIdx.x, tid = threadIdx.x;
    int wid = tid >> 5, lane = tid & 31;
    int i = b * 1024 + tid;
    int v = (i < N_NODES) ? g_zeroed[i] : 0;

    int incl = warp_incl_scan(v, lane);
    if (lane == 31) wsum[wid] = incl;
    __syncthreads();

    if (wid == 0) {
        int ws = wsum[lane];
        int wi = warp_incl_scan(ws, lane);
        wsum[lane] = wi - ws;                     // exclusive warp prefix
        int tot = __shfl_sync(0xffffffffu, wi, 31);

        if (lane == 0)
            look[b] = ((unsigned long long)(b == 0 ? 2u : 1u) << 32) | (unsigned)tot;

        int excl = 0;
        if (b > 0) {
            int win = b - 1;
            while (true) {
                int j = win - lane;
                unsigned long long s = 0;
                if (j >= 0) {
                    do { s = look[j]; } while ((unsigned)(s >> 32) == 0u);
                }
                unsigned flag = (j >= 0) ? (unsigned)(s >> 32) : 0u;
                int val = (int)(unsigned)s;
                unsigned mask = __ballot_sync(0xffffffffu, flag == 2u);
                int contrib;
                if (mask) {
                    int lz = __ffs(mask) - 1;
                    contrib = (lane <= lz && j >= 0) ? val : 0;
                } else {
                    contrib = (j >= 0) ? val : 0;
                }
                #pragma unroll
                for (int o = 16; o > 0; o >>= 1)
                    contrib += __shfl_xor_sync(0xffffffffu, contrib, o);
                excl += contrib;
                if (mask) break;
                win -= 32;
            }
            if (lane == 0)
                look[b] = (2ULL << 32) | (unsigned)(excl + tot);
        }
        if (lane == 0) sh_excl = excl;
    }
    __syncthreads();

    int inclusive = sh_excl + wsum[wid] + incl;
    if (i < N_NODES) {
        g_off[i + 1]  = inclusive;
        g_cur[i]      = inclusive - v;
        g_deginv[i]   = (v > 0) ? (1.0f / (float)v) : 0.0f;
        if (i == 0) g_off[0] = 0;
    }
}

__global__ void fill_kernel(const int* __restrict__ src, const int* __restrict__ dst) {
    int i = blockIdx.x * blockDim.x + threadIdx.x;
    if (i < N_EDGES) {
        int d   = dst[i];
        int pos = atomicAdd(&g_cur[d], 1);
        g_col[pos] = src[i];
    }
}

// ---------------- layer 1 (K = 3, fp32 math, fp16 output) ----------------
// Gather: 4 lanes/node with clamped double-issue. Epilogue: thread = (col-pair,
// node-half) -> 32 iterations with half2 coalesced stores.
__global__ void layer1_kernel(const float* __restrict__ Wl,
                              const float* __restrict__ Wr,
                              const float* __restrict__ b,
                              __half* __restrict__ hout) {
    __shared__ __align__(16) float aggx[64][4];
    __shared__ __align__(16) float xs[64][4];
    int tid  = threadIdx.x;
    int warp = tid >> 5, lane = tid & 31;
    int sub  = lane >> 2, sl = lane & 3;        // 8 sub-groups of 4 lanes
    int base = blockIdx.x * 64;

    #pragma unroll
    for (int pass = 0; pass < 2; pass++) {
        int n = pass * 32 + warp * 8 + sub;     // 0..63
        int node = base + n;
        if (node < N_NODES) {
            int s0 = g_off[node], e0 = g_off[node + 1];
            int safe = min(s0, N_EDGES - 1);
            float a0 = 0.f, a1 = 0.f, a2 = 0.f;
            float b0 = 0.f, b1 = 0.f, b2 = 0.f;
            for (int w = s0; w < e0; w += 8) {
                int i0 = w + sl, i1 = w + sl + 4;
                bool p0 = i0 < e0, p1 = i1 < e0;
                int j0 = g_col[p0 ? i0 : safe];
                int j1 = g_col[p1 ? i1 : safe];
                float4 v0 = g_x4[j0];
                float4 v1 = g_x4[j1];
                if (p0) { a0 += v0.x; a1 += v0.y; a2 += v0.z; }
                if (p1) { b0 += v1.x; b1 += v1.y; b2 += v1.z; }
            }
            a0 += b0; a1 += b1; a2 += b2;
            #pragma unroll
            for (int o = 1; o < 4; o <<= 1) {
                a0 += __shfl_xor_sync(0xffffffffu, a0, o);
                a1 += __shfl_xor_sync(0xffffffffu, a1, o);
                a2 += __shfl_xor_sync(0xffffffffu, a2, o);
            }
            if (sl == 0) {
                float di = g_deginv[node];
                float4 agg = make_float4(a0 * di, a1 * di, a2 * di, 0.0f);
                *(float4*)&aggx[n][0] = agg;
                *(float4*)&xs[n][0] = g_x4[node];
            }
        }
    }
    __syncthreads();

    // epilogue: col pair = 2*(tid&63), node half = tid>>6 (32 nodes each)
    int c2  = tid & 63;
    int g2  = tid >> 6;
    int col = c2 * 2;
    float wl0a = Wl[0 * CH + col],     wl1a = Wl[1 * CH + col],     wl2a = Wl[2 * CH + col];
    float wl0b = Wl[0 * CH + col + 1], wl1b = Wl[1 * CH + col + 1], wl2b = Wl[2 * CH + col + 1];
    float wr0a = Wr[0 * CH + col],     wr1a = Wr[1 * CH + col],     wr2a = Wr[2 * CH + col];
    float wr0b = Wr[0 * CH + col + 1], wr1b = Wr[1 * CH + col + 1], wr2b = Wr[2 * CH + col + 1];
    float bb0 = b[col], bb1 = b[col + 1];

    int nend = min(g2 * 32 + 32, N_NODES - base);
    for (int n = g2 * 32; n < nend; n++) {
        float4 ag = *(const float4*)&aggx[n][0];
        float4 ow = *(const float4*)&xs[n][0];
        float acc0 = bb0 + ag.x * wl0a + ag.y * wl1a + ag.z * wl2a
                         + ow.x * wr0a + ow.y * wr1a + ow.z * wr2a;
        float acc1 = bb1 + ag.x * wl0b + ag.y * wl1b + ag.z * wl2b
                         + ow.x * wr0b + ow.y * wr1b + ow.z * wr2b;
        __half2 hv = __floats2half2_rn(fmaxf(acc0, 0.0f), fmaxf(acc1, 0.0f));
        *(__half2*)&hout[(size_t)(base + n) * CH + col] = hv;
    }
}

// ---------------- layers 2/3: dual-buffer single-sync fp16 TC GEMM ----------------
// As[0] = agg (gather), As[1] = own rows; ONE sync; then both mma passes
// back-to-back (pass p reads As[p] against Wt's pass-p fragments).
template <bool HALF_OUT>
__global__ void __launch_bounds__(256, 4)
layerTC_kernel(const __half* __restrict__ hin, void* __restrict__ hout_v,
               const __half* __restrict__ Wt, const float* __restrict__ bias) {
    __shared__ __align__(16) unsigned As[2][NPB * AS_H2];   // 34.8 KB

    int tid  = threadIdx.x;
    int warp = tid >> 5, lane = tid & 31;
    int base = blockIdx.x * NPB;

    int wm = warp >> 2;          // 0..1  -> M rows [wm*32, wm*32+32)
    int wn = warp & 3;           // 0..3  -> N cols [wn*32, wn*32+32)
    int gid = lane >> 2, tig = lane & 3;

    float acc[2][4][4];
    #pragma unroll
    for (int mt = 0; mt < 2; mt++)
        #pragma unroll
        for (int nt = 0; nt < 4; nt++)
            #pragma unroll
            for (int r = 0; r < 4; r++) acc[mt][nt][r] = 0.0f;

    const uint4* Wf = (const uint4*)Wt;

    // ---- Phase A: gather into As[0]; own rows into As[1]; one sync ----
    #pragma unroll
    for (int q = 0; q < 4; q++) {
        int nA = warp + q * 16;           // rows warp, warp+16, warp+32, warp+48
        int nB = nA + 8;
        int nodeA = base + nA, nodeB = base + nB;
        bool okA = nodeA < N_NODES, okB = nodeB < N_NODES;
        int sA = okA ? g_off[nodeA] : 0, eA = okA ? g_off[nodeA + 1] : 0;
        int sB = okB ? g_off[nodeB] : 0, eB = okB ? g_off[nodeB + 1] : 0;
        int safeA = min(sA, N_EDGES - 1);
        int safeB = min(sB, N_EDGES - 1);
        int maxd = max(eA - sA, eB - sB);

        float4 A0 = make_float4(0.f, 0.f, 0.f, 0.f);
        float4 A1 = A0, B0 = A0, B1 = A0;

        for (int w = 0; w < maxd; w += 4) {
            int ja[4], jb[4];
            bool pa[4], pb[4];
            #pragma unroll
            for (int j = 0; j < 4; j++) {
                int ia = sA + w + j, ib = sB + w + j;
                pa[j] = ia < eA;  pb[j] = ib < eB;
                ja[j] = g_col[pa[j] ? ia : safeA];
                jb[j] = g_col[pb[j] ? ib : safeB];
            }
            uint2 va0 = *(const uint2*)&hin[(size_t)ja[0] * CH + lane * 4];
            uint2 va1 = *(const uint2*)&hin[(size_t)ja[1] * CH + lane * 4];
            uint2 va2 = *(const uint2*)&hin[(size_t)ja[2] * CH + lane * 4];
            uint2 va3 = *(const uint2*)&hin[(size_t)ja[3] * CH + lane * 4];
            uint2 vb0 = *(const uint2*)&hin[(size_t)jb[0] * CH + lane * 4];
            uint2 vb1 = *(const uint2*)&hin[(size_t)jb[1] * CH + lane * 4];
            uint2 vb2 = *(const uint2*)&hin[(size_t)jb[2] * CH + lane * 4];
            uint2 vb3 = *(const uint2*)&hin[(size_t)jb[3] * CH + lane * 4];
            if (pa[0]) acc4_h2(A0, va0);
            if (pa[1]) acc4_h2(A1, va1);
            if (pa[2]) acc4_h2(A0, va2);
            if (pa[3]) acc4_h2(A1, va3);
            if (pb[0]) acc4_h2(B0, vb0);
            if (pb[1]) acc4_h2(B1, vb1);
            if (pb[2]) acc4_h2(B0, vb2);
            if (pb[3]) acc4_h2(B1, vb3);
        }

        if (okA) {
            float di = g_deginv[nodeA];
            uint2 st;
            st.x = h2u(__floats2half2_rn((A0.x + A1.x) * di, (A0.y + A1.y) * di));
            st.y = h2u(__floats2half2_rn((A0.z + A1.z) * di, (A0.w + A1.w) * di));
            *(uint2*)&As[0][nA * AS_H2 + lane * 2] = st;
            uint2 own = *(const uint2*)&hin[(size_t)nodeA * CH + lane * 4];
            *(uint2*)&As[1][nA * AS_H2 + lane * 2] = own;
        }
        if (okB) {
            float di = g_deginv[nodeB];
            uint2 st;
            st.x = h2u(__floats2half2_rn((B0.x + B1.x) * di, (B0.y + B1.y) * di));
            st.y = h2u(__floats2half2_rn((B0.z + B1.z) * di, (B0.w + B1.w) * di));
            *(uint2*)&As[0][nB * AS_H2 + lane * 2] = st;
            uint2 own = *(const uint2*)&hin[(size_t)nodeB * CH + lane * 4];
            *(uint2*)&As[1][nB * AS_H2 + lane * 2] = own;
        }
    }
    __syncthreads();

    // ---- Phase B: both passes back-to-back ----
    #pragma unroll
    for (int pass = 0; pass < 2; pass++) {
        #pragma unroll
        for (int kt = 0; kt < 8; kt++) {
            unsigned i0 = ((((unsigned)(wn * 2 + pass) * 8 + kt) * 2) * 32) + lane;
            uint4 q0 = Wf[i0];        // nt 0,1
            uint4 q1 = Wf[i0 + 32];   // nt 2,3
            unsigned bfr[4][2] = {
                { q0.x, q0.y }, { q0.z, q0.w },
                { q1.x, q1.y }, { q1.z, q1.w } };

            unsigned kc = kt * 8;     // half2 column base within row
            #pragma unroll
            for (int mt = 0; mt < 2; mt++) {
                unsigned r0 = (unsigned)(wm * 32 + mt * 16 + gid) * AS_H2 + kc + tig;
                unsigned a[4];
                a[0] = As[pass][r0];
                a[1] = As[pass][r0 + 8 * AS_H2];
                a[2] = As[pass][r0 + 4];
                a[3] = As[pass][r0 + 8 * AS_H2 + 4];
                #pragma unroll
                for (int nt = 0; nt < 4; nt++)
                    mma_f16(acc[mt][nt], a, bfr[nt]);
            }
        }
    }

    // ---- epilogue: bias + relu + store ----
    #pragma unroll
    for (int nt = 0; nt < 4; nt++) {
        int col = wn * 32 + nt * 8 + tig * 2;
        float bb0 = bias[col], bb1 = bias[col + 1];
        #pragma unroll
        for (int mt = 0; mt < 2; mt++) {
            int row = base + wm * 32 + mt * 16 + gid;
            #pragma unroll
            for (int half_row = 0; half_row < 2; half_row++) {
                int r = row + half_row * 8;
                if (r >= N_NODES) continue;
                float vx = fmaxf(acc[mt][nt][half_row * 2 + 0] + bb0, 0.0f);
                float vy = fmaxf(acc[mt][nt][half_row * 2 + 1] + bb1, 0.0f);
                if (HALF_OUT) {
                    __half* ho = (__half*)hout_v;
                    __half2 hv = __floats2half2_rn(vx, vy);
                    *(__half2*)&ho[(size_t)r * CH + col] = hv;
                } else {
                    float* fo = (float*)hout_v;
                    float2 fv = make_float2(vx, vy);
                    *(float2*)&fo[(size_t)r * CH + col] = fv;
                }
            }
        }
    }
}

// ---------------- launch ----------------
extern "C" void kernel_launch(void* const* d_in, const int* in_sizes, int n_in,
                              void* d_out, int out_size) {
    const float* x   = (const float*)d_in[0];
    const int*   ei  = (const int*)d_in[1];      // [2, E]
    const float* W1l = (const float*)d_in[2];
    const float* W1r = (const float*)d_in[3];
    const float* b1  = (const float*)d_in[4];
    const float* W2l = (const float*)d_in[5];
    const float* W2r = (const float*)d_in[6];
    const float* b2  = (const float*)d_in[7];
    const float* W3l = (const float*)d_in[8];
    const float* W3r = (const float*)d_in[9];
    const float* b3  = (const float*)d_in[10];
    float* out = (float*)d_out;

    const int* src = ei;
    const int* dst = ei + N_EDGES;

    __half* h1; __half* h2; __half* Wt2; __half* Wt3; int* zp;
    cudaGetSymbolAddress((void**)&h1, g_h1);
    cudaGetSymbolAddress((void**)&h2, g_h2);
    cudaGetSymbolAddress((void**)&Wt2, g_Wt2);
    cudaGetSymbolAddress((void**)&Wt3, g_Wt3);
    cudaGetSymbolAddress((void**)&zp, g_zeroed);

    // one memset covers deg histogram + lookback flags
    cudaMemsetAsync(zp, 0, ZCOUNT * sizeof(int));
    histprep_kernel<<<PREP_BLOCKS + XPAD_BLOCKS + (N_EDGES + 255) / 256, 256>>>(
        dst, x, W2l, W2r, W3l, W3r);
    scanlb_kernel<<<NCHUNK, 1024>>>();
    fill_kernel<<<(N_EDGES + 255) / 256, 256>>>(src, dst);

    // layers
    layer1_kernel<<<(N_NODES + 63) / 64, 128>>>(W1l, W1r, b1, h1);
    layerTC_kernel<true><<<NBLK, 256>>>(h1, (void*)h2, Wt2, b2);
    layerTC_kernel<false><<<NBLK, 256>>>(h2, (void*)out, Wt3, b3);
}